// round 1
// baseline (speedup 1.0000x reference)
#include <cuda_runtime.h>
#include <math.h>

// Problem dims (fixed by the reference).
#define SEQ 4096
#define DIM 1024

// Scratch: Q, K, V [SEQ, DIM] and scores S [SEQ, SEQ]. Static __device__
// arrays (no cudaMalloc allowed anywhere).
__device__ float g_Q[(size_t)SEQ * DIM];
__device__ float g_K[(size_t)SEQ * DIM];
__device__ float g_V[(size_t)SEQ * DIM];
__device__ float g_S[(size_t)SEQ * SEQ];

// ============================================================================
// Tiled fp32 SGEMM.
//   C[M,N] = alpha * A[M,K] * op(B) + bias
//   TRANSB=false: B is [K,N] row-major (NN)
//   TRANSB=true : B is [N,K] row-major (NT, i.e. C = A * B^T)
// BM=BN=128, BK=16, 256 threads, 8x8 per-thread tile.
// Requires M%128==0, N%128==0, K%16==0 (true for all calls here).
// ============================================================================
template <bool TRANSB, bool BIAS>
__global__ __launch_bounds__(256, 2)
void sgemm128(const float* __restrict__ A, const float* __restrict__ B,
              const float* __restrict__ bias, float* __restrict__ C,
              int M, int N, int K, float alpha) {
    constexpr int BM = 128, BN = 128, BK = 16, TM = 8, TN = 8;
    // +4 pad keeps float4 alignment (132 % 4 == 0) and breaks bank conflicts.
    __shared__ float As[BK][BM + 4];
    __shared__ float Bs[BK][BN + 4];

    const int tid  = threadIdx.x;
    const int row0 = blockIdx.y * BM;
    const int col0 = blockIdx.x * BN;
    const int tx   = tid & 15;   // 0..15 -> column group
    const int ty   = tid >> 4;   // 0..15 -> row group

    float acc[TM][TN] = {};
    float ra[TM], rb[TN];

    for (int k0 = 0; k0 < K; k0 += BK) {
        // ---- load A tile (BM x BK), transposed into As[k][m] ----
        #pragma unroll
        for (int i = 0; i < 2; i++) {
            int idx = tid + i * 256;            // 0..511
            int m   = idx >> 2;                 // 0..127
            int kc  = (idx & 3) * 4;            // 0,4,8,12
            float4 v = *reinterpret_cast<const float4*>(
                &A[(size_t)(row0 + m) * K + k0 + kc]);
            As[kc + 0][m] = v.x;
            As[kc + 1][m] = v.y;
            As[kc + 2][m] = v.z;
            As[kc + 3][m] = v.w;
        }
        // ---- load B tile ----
        if (TRANSB) {
            // B[N,K]: rows col0..col0+127, cols k0..k0+15, transpose into Bs[k][n]
            #pragma unroll
            for (int i = 0; i < 2; i++) {
                int idx = tid + i * 256;
                int n   = idx >> 2;
                int kc  = (idx & 3) * 4;
                float4 v = *reinterpret_cast<const float4*>(
                    &B[(size_t)(col0 + n) * K + k0 + kc]);
                Bs[kc + 0][n] = v.x;
                Bs[kc + 1][n] = v.y;
                Bs[kc + 2][n] = v.z;
                Bs[kc + 3][n] = v.w;
            }
        } else {
            // B[K,N]: rows k0..k0+15, cols col0..col0+127 (contiguous -> float4)
            #pragma unroll
            for (int i = 0; i < 2; i++) {
                int idx = tid + i * 256;        // 0..511
                int kk  = idx >> 5;             // 0..15
                int nc  = (idx & 31) * 4;       // 0..124
                float4 v = *reinterpret_cast<const float4*>(
                    &B[(size_t)(k0 + kk) * N + col0 + nc]);
                *reinterpret_cast<float4*>(&Bs[kk][nc]) = v;
            }
        }
        __syncthreads();

        // ---- compute ----
        #pragma unroll
        for (int k = 0; k < BK; k++) {
            #pragma unroll
            for (int i = 0; i < TM; i++) ra[i] = As[k][ty * TM + i];
            #pragma unroll
            for (int j = 0; j < TN; j++) rb[j] = Bs[k][tx * TN + j];
            #pragma unroll
            for (int i = 0; i < TM; i++)
                #pragma unroll
                for (int j = 0; j < TN; j++)
                    acc[i][j] = fmaf(ra[i], rb[j], acc[i][j]);
        }
        __syncthreads();
    }

    // ---- epilogue ----
    #pragma unroll
    for (int i = 0; i < TM; i++) {
        int r = row0 + ty * TM + i;
        #pragma unroll
        for (int j = 0; j < TN; j += 4) {
            int c = col0 + tx * TN + j;
            float4 v;
            v.x = acc[i][j + 0] * alpha;
            v.y = acc[i][j + 1] * alpha;
            v.z = acc[i][j + 2] * alpha;
            v.w = acc[i][j + 3] * alpha;
            if (BIAS) {
                v.x += bias[c + 0];
                v.y += bias[c + 1];
                v.z += bias[c + 2];
                v.w += bias[c + 3];
            }
            *reinterpret_cast<float4*>(&C[(size_t)r * N + c]) = v;
        }
    }
}

// ============================================================================
// Row softmax over S[SEQ, SEQ], in place. One block per row, 256 threads.
// ============================================================================
__global__ __launch_bounds__(256)
void softmax_rows(float* __restrict__ S, int n) {
    const int row = blockIdx.x;
    float4* p = reinterpret_cast<float4*>(S + (size_t)row * n);
    const int nv = n / 4;            // 1024 float4s
    const int tid = threadIdx.x;
    __shared__ float red[256];

    // pass 1: max
    float m = -INFINITY;
    for (int i = tid; i < nv; i += 256) {
        float4 v = p[i];
        m = fmaxf(m, fmaxf(fmaxf(v.x, v.y), fmaxf(v.z, v.w)));
    }
    red[tid] = m;
    __syncthreads();
    for (int s = 128; s > 0; s >>= 1) {
        if (tid < s) red[tid] = fmaxf(red[tid], red[tid + s]);
        __syncthreads();
    }
    m = red[0];
    __syncthreads();

    // pass 2: exp + sum
    float sum = 0.0f;
    for (int i = tid; i < nv; i += 256) {
        float4 v = p[i];
        v.x = expf(v.x - m);
        v.y = expf(v.y - m);
        v.z = expf(v.z - m);
        v.w = expf(v.w - m);
        sum += (v.x + v.y) + (v.z + v.w);
        p[i] = v;
    }
    red[tid] = sum;
    __syncthreads();
    for (int s = 128; s > 0; s >>= 1) {
        if (tid < s) red[tid] += red[tid + s];
        __syncthreads();
    }
    const float inv = 1.0f / red[0];
    __syncthreads();

    // pass 3: normalize
    for (int i = tid; i < nv; i += 256) {
        float4 v = p[i];
        v.x *= inv; v.y *= inv; v.z *= inv; v.w *= inv;
        p[i] = v;
    }
}

// ============================================================================
// kernel_launch
// ============================================================================
extern "C" void kernel_launch(void* const* d_in, const int* in_sizes, int n_in,
                              void* d_out, int out_size) {
    const float* x  = (const float*)d_in[0];
    const float* WQ = (const float*)d_in[1];
    const float* WK = (const float*)d_in[2];
    const float* WV = (const float*)d_in[3];
    const float* bQ = (const float*)d_in[4];
    const float* bK = (const float*)d_in[5];
    const float* bV = (const float*)d_in[6];
    float* out = (float*)d_out;

    float *Q, *K, *V, *S;
    cudaGetSymbolAddress((void**)&Q, g_Q);
    cudaGetSymbolAddress((void**)&K, g_K);
    cudaGetSymbolAddress((void**)&V, g_V);
    cudaGetSymbolAddress((void**)&S, g_S);

    dim3 blk(256);

    // QKV projections: [SEQ,DIM] = x[SEQ,DIM] @ W[DIM,DIM] + b  (NN)
    dim3 gProj(DIM / 128, SEQ / 128);
    sgemm128<false, true><<<gProj, blk>>>(x, WQ, bQ, Q, SEQ, DIM, DIM, 1.0f);
    sgemm128<false, true><<<gProj, blk>>>(x, WK, bK, K, SEQ, DIM, DIM, 1.0f);
    sgemm128<false, true><<<gProj, blk>>>(x, WV, bV, V, SEQ, DIM, DIM, 1.0f);

    // Scores: S = (Q @ K^T) / sqrt(D)   (NT), 1/sqrt(1024) = 0.03125
    dim3 gScore(SEQ / 128, SEQ / 128);
    sgemm128<true, false><<<gScore, blk>>>(Q, K, nullptr, S, SEQ, SEQ, DIM,
                                           0.03125f);

    // Softmax over rows of S, in place.
    softmax_rows<<<SEQ, blk>>>(S, SEQ);

    // Output: out = P @ V   (NN, K = SEQ)
    dim3 gOut(DIM / 128, SEQ / 128);
    sgemm128<false, false><<<gOut, blk>>>(S, V, nullptr, out, SEQ, DIM, SEQ,
                                          1.0f);
}

// round 3
// speedup vs baseline: 2.2495x; 2.2495x over previous
#include <cuda_runtime.h>
#include <cuda_bf16.h>
#include <math.h>
#include <stdint.h>

#define SEQ 4096
#define DIM 1024

// ======================= device scratch (no cudaMalloc allowed) ============
__device__ float          g_S[(size_t)SEQ * SEQ];          // scores fp32
__device__ unsigned short g_xhi[(size_t)SEQ * DIM], g_xlo[(size_t)SEQ * DIM];
__device__ unsigned short g_wqhi[(size_t)DIM * DIM], g_wqlo[(size_t)DIM * DIM];
__device__ unsigned short g_wkhi[(size_t)DIM * DIM], g_wklo[(size_t)DIM * DIM];
__device__ unsigned short g_wvhi[(size_t)DIM * DIM], g_wvlo[(size_t)DIM * DIM];
__device__ unsigned short g_qhi[(size_t)SEQ * DIM], g_qlo[(size_t)SEQ * DIM];
__device__ unsigned short g_khi[(size_t)SEQ * DIM], g_klo[(size_t)SEQ * DIM];
__device__ unsigned short g_vthi[(size_t)DIM * SEQ], g_vtlo[(size_t)DIM * SEQ]; // V^T
__device__ unsigned short g_phi[(size_t)SEQ * SEQ], g_plo[(size_t)SEQ * SEQ];   // probs

// ======================= helpers ===========================================
__device__ __forceinline__ uint32_t smem_u32(const void* p) {
    uint32_t a;
    asm("{ .reg .u64 t; cvta.to.shared.u64 t, %1; cvt.u32.u64 %0, t; }"
        : "=r"(a) : "l"(p));
    return a;
}
__device__ __forceinline__ void cpasync16(uint32_t dst, const void* src) {
    asm volatile("cp.async.cg.shared.global [%0], [%1], 16;"
                 :: "r"(dst), "l"(src));
}
#define CP_COMMIT() asm volatile("cp.async.commit_group;" ::: "memory")
#define CP_WAIT(n)  asm volatile("cp.async.wait_group %0;" :: "n"(n) : "memory")

#define LDSM4(r0, r1, r2, r3, addr)                                          \
    asm volatile("ldmatrix.sync.aligned.m8n8.x4.shared.b16 {%0,%1,%2,%3}, [%4];" \
                 : "=r"(r0), "=r"(r1), "=r"(r2), "=r"(r3) : "r"(addr))

#define MMA16816(c, a0, a1, a2, a3, b0, b1)                                  \
    asm volatile("mma.sync.aligned.m16n8k16.row.col.f32.bf16.bf16.f32 "      \
                 "{%0,%1,%2,%3}, {%4,%5,%6,%7}, {%8,%9}, {%0,%1,%2,%3};"     \
                 : "+f"((c)[0]), "+f"((c)[1]), "+f"((c)[2]), "+f"((c)[3])    \
                 : "r"(a0), "r"(a1), "r"(a2), "r"(a3), "r"(b0), "r"(b1))

__device__ __forceinline__ void split2(float v, unsigned short& h, unsigned short& l) {
    __nv_bfloat16 bh = __float2bfloat16(v);
    __nv_bfloat16 bl = __float2bfloat16(v - __bfloat162float(bh));
    h = __bfloat16_as_ushort(bh);
    l = __bfloat16_as_ushort(bl);
}

// ======================= GEMM: C[M,N] = alpha*(A @ B^T) + bias =============
// A [M,K] hi/lo bf16 K-major, B [N,K] hi/lo bf16 K-major.
// CTA tile 128x128, BK=32, 8 warps (2x4), warp tile 64x32, bf16x3 split.
enum { EPI_F32 = 0, EPI_SPLIT = 1, EPI_SPLIT_T = 2 };

#define PITCH 80            // 32 bf16 (64B) + 16B pad per row
#define T_OFF_AL 10240
#define T_OFF_BH 20480
#define T_OFF_BL 30720
#define STG_BYTES 40960
#define SMEM_DYN (3 * STG_BYTES)   // 122880; epilogue T reuse: 128*133*4=68096

__device__ __forceinline__ void load_stage(
    uint32_t sb, int slot, int kt, int tid,
    const unsigned short* __restrict__ Ahi, const unsigned short* __restrict__ Alo,
    const unsigned short* __restrict__ Bhi, const unsigned short* __restrict__ Blo,
    int row0, int col0, int K) {
    uint32_t s0 = sb + slot * STG_BYTES;
    int k0 = kt << 5;
#pragma unroll
    for (int p = 0; p < 2; p++) {
        int idx = tid + p * 256;
        int r = idx >> 2, c = idx & 3;
        uint32_t d = s0 + r * PITCH + c * 16;
        size_t ga = (size_t)(row0 + r) * K + k0 + c * 8;
        size_t gb = (size_t)(col0 + r) * K + k0 + c * 8;
        cpasync16(d, Ahi + ga);
        cpasync16(d + T_OFF_AL, Alo + ga);
        cpasync16(d + T_OFF_BH, Bhi + gb);
        cpasync16(d + T_OFF_BL, Blo + gb);
    }
}

template <int EPI, bool BIAS>
__global__ __launch_bounds__(256, 1)
void gemm_mma(const unsigned short* __restrict__ Ahi, const unsigned short* __restrict__ Alo,
              const unsigned short* __restrict__ Bhi, const unsigned short* __restrict__ Blo,
              const float* __restrict__ bias,
              float* __restrict__ Cf,
              unsigned short* __restrict__ Chi, unsigned short* __restrict__ Clo,
              int M, int N, int K, int ldct, float alpha) {
    extern __shared__ char smem[];
    const uint32_t sb = smem_u32(smem);
    const int tid = threadIdx.x;
    const int lane = tid & 31;
    const int w = tid >> 5;
    const int wm = w >> 2;          // 0..1
    const int wn = w & 3;           // 0..3
    const int row0 = blockIdx.y * 128;
    const int col0 = blockIdx.x * 128;

    float acc[4][4][4] = {};        // [mi][ni][reg]

    const int nk = K >> 5;

    // per-lane ldmatrix offsets (bytes)
    const uint32_t aoff = ((lane & 7) + ((lane >> 3) & 1) * 8) * PITCH
                        + ((lane >> 4) & 1) * 16;
    const uint32_t boff = ((lane & 7) + ((lane >> 4) & 1) * 8) * PITCH
                        + ((lane >> 3) & 1) * 16;

    load_stage(sb, 0, 0, tid, Ahi, Alo, Bhi, Blo, row0, col0, K);
    CP_COMMIT();
    load_stage(sb, 1, 1, tid, Ahi, Alo, Bhi, Blo, row0, col0, K);
    CP_COMMIT();

    int slot = 0;
    for (int kt = 0; kt < nk; kt++) {
        CP_WAIT(1);
        __syncthreads();
        if (kt + 2 < nk) {
            int ns = slot + 2; if (ns >= 3) ns -= 3;
            load_stage(sb, ns, kt + 2, tid, Ahi, Alo, Bhi, Blo, row0, col0, K);
        }
        CP_COMMIT();

        const uint32_t s0 = sb + slot * STG_BYTES;
        const uint32_t aB = s0 + (wm * 64) * PITCH + aoff;
        const uint32_t bB = s0 + T_OFF_BH + (wn * 32) * PITCH + boff;
#pragma unroll
        for (int ks = 0; ks < 2; ks++) {
            uint32_t ah[4][4], al[4][4], bh[4][2], bl[4][2];
#pragma unroll
            for (int mi = 0; mi < 4; mi++) {
                uint32_t a = aB + mi * (16 * PITCH) + ks * 32;
                LDSM4(ah[mi][0], ah[mi][1], ah[mi][2], ah[mi][3], a);
                LDSM4(al[mi][0], al[mi][1], al[mi][2], al[mi][3], a + T_OFF_AL);
            }
#pragma unroll
            for (int j = 0; j < 2; j++) {
                uint32_t b = bB + j * (16 * PITCH) + ks * 32;
                LDSM4(bh[2 * j][0], bh[2 * j][1], bh[2 * j + 1][0], bh[2 * j + 1][1], b);
                LDSM4(bl[2 * j][0], bl[2 * j][1], bl[2 * j + 1][0], bl[2 * j + 1][1],
                      b + (T_OFF_BL - T_OFF_BH));
            }
#pragma unroll
            for (int mi = 0; mi < 4; mi++)
#pragma unroll
                for (int ni = 0; ni < 4; ni++) {
                    MMA16816(acc[mi][ni], ah[mi][0], ah[mi][1], ah[mi][2], ah[mi][3],
                             bh[ni][0], bh[ni][1]);
                    MMA16816(acc[mi][ni], ah[mi][0], ah[mi][1], ah[mi][2], ah[mi][3],
                             bl[ni][0], bl[ni][1]);
                    MMA16816(acc[mi][ni], al[mi][0], al[mi][1], al[mi][2], al[mi][3],
                             bh[ni][0], bh[ni][1]);
                }
        }
        slot++; if (slot >= 3) slot = 0;
    }

    CP_WAIT(0);
    __syncthreads();

    const int tr = lane >> 2;          // 0..7
    const int tc = (lane & 3) * 2;     // 0,2,4,6

    if (EPI == EPI_SPLIT_T) {
        // stage fp32 tile in smem, then transposed, coalesced split stores
        float* T = reinterpret_cast<float*>(smem);   // [128][133]
#pragma unroll
        for (int mi = 0; mi < 4; mi++)
#pragma unroll
            for (int ni = 0; ni < 4; ni++) {
                int r = wm * 64 + mi * 16 + tr;
                int c = wn * 32 + ni * 8 + tc;
                T[r * 133 + c]       = acc[mi][ni][0];
                T[r * 133 + c + 1]   = acc[mi][ni][1];
                T[(r + 8) * 133 + c]     = acc[mi][ni][2];
                T[(r + 8) * 133 + c + 1] = acc[mi][ni][3];
            }
        __syncthreads();
        const int m = tid & 127;
        const int half = tid >> 7;
#pragma unroll 1
        for (int n = half; n < 128; n += 2) {
            float v = T[m * 133 + n] * alpha;
            if (BIAS) v += bias[col0 + n];
            unsigned short h, l;
            split2(v, h, l);
            size_t o = (size_t)(col0 + n) * ldct + row0 + m;
            Chi[o] = h;
            Clo[o] = l;
        }
    } else {
#pragma unroll
        for (int mi = 0; mi < 4; mi++)
#pragma unroll
            for (int ni = 0; ni < 4; ni++) {
                int r = row0 + wm * 64 + mi * 16 + tr;
                int c = col0 + wn * 32 + ni * 8 + tc;
#pragma unroll
                for (int hh = 0; hh < 2; hh++) {
                    int rr = r + hh * 8;
                    float v0 = acc[mi][ni][2 * hh + 0] * alpha;
                    float v1 = acc[mi][ni][2 * hh + 1] * alpha;
                    if (BIAS) { v0 += bias[c]; v1 += bias[c + 1]; }
                    if (EPI == EPI_F32) {
                        float2 f2 = make_float2(v0, v1);
                        *reinterpret_cast<float2*>(&Cf[(size_t)rr * N + c]) = f2;
                    } else {
                        unsigned short h0, l0, h1, l1;
                        split2(v0, h0, l0);
                        split2(v1, h1, l1);
                        uint32_t hp = (uint32_t)h0 | ((uint32_t)h1 << 16);
                        uint32_t lp = (uint32_t)l0 | ((uint32_t)l1 << 16);
                        *reinterpret_cast<uint32_t*>(&Chi[(size_t)rr * N + c]) = hp;
                        *reinterpret_cast<uint32_t*>(&Clo[(size_t)rr * N + c]) = lp;
                    }
                }
            }
    }
}

// ======================= elementwise split (x) =============================
__global__ __launch_bounds__(256)
void split_kernel(const float* __restrict__ in, unsigned short* __restrict__ hi,
                  unsigned short* __restrict__ lo, int n4) {
    int i = blockIdx.x * 256 + threadIdx.x;
    if (i >= n4) return;
    float4 v = reinterpret_cast<const float4*>(in)[i];
    unsigned short h[4], l[4];
    split2(v.x, h[0], l[0]);
    split2(v.y, h[1], l[1]);
    split2(v.z, h[2], l[2]);
    split2(v.w, h[3], l[3]);
    reinterpret_cast<uint2*>(hi)[i] = *reinterpret_cast<uint2*>(h);
    reinterpret_cast<uint2*>(lo)[i] = *reinterpret_cast<uint2*>(l);
}

// ======================= split + transpose (W -> W^T) ======================
__global__ __launch_bounds__(256)
void splitT_kernel(const float* __restrict__ in, unsigned short* __restrict__ hiT,
                   unsigned short* __restrict__ loT, int R, int C) {
    __shared__ float t[32][33];
    const int tx = threadIdx.x & 31, ty = threadIdx.x >> 5;
    const int bc = blockIdx.x * 32, br = blockIdx.y * 32;
#pragma unroll
    for (int j = 0; j < 4; j++)
        t[ty + 8 * j][tx] = in[(size_t)(br + ty + 8 * j) * C + bc + tx];
    __syncthreads();
#pragma unroll
    for (int j = 0; j < 4; j++) {
        int cc = ty + 8 * j;
        unsigned short h, l;
        split2(t[tx][cc], h, l);
        hiT[(size_t)(bc + cc) * R + br + tx] = h;
        loT[(size_t)(bc + cc) * R + br + tx] = l;
    }
}

// ======================= softmax rows + split output =======================
__global__ __launch_bounds__(256)
void softmax_split(float* __restrict__ S, unsigned short* __restrict__ phi,
                   unsigned short* __restrict__ plo, int n) {
    const int row = blockIdx.x;
    float4* p = reinterpret_cast<float4*>(S + (size_t)row * n);
    const int nv = n / 4;
    const int tid = threadIdx.x;
    __shared__ float red[256];

    float m = -INFINITY;
    for (int i = tid; i < nv; i += 256) {
        float4 v = p[i];
        m = fmaxf(m, fmaxf(fmaxf(v.x, v.y), fmaxf(v.z, v.w)));
    }
    red[tid] = m;
    __syncthreads();
    for (int s = 128; s > 0; s >>= 1) {
        if (tid < s) red[tid] = fmaxf(red[tid], red[tid + s]);
        __syncthreads();
    }
    m = red[0];
    __syncthreads();

    float sum = 0.0f;
    for (int i = tid; i < nv; i += 256) {
        float4 v = p[i];
        v.x = expf(v.x - m);
        v.y = expf(v.y - m);
        v.z = expf(v.z - m);
        v.w = expf(v.w - m);
        sum += (v.x + v.y) + (v.z + v.w);
        p[i] = v;
    }
    red[tid] = sum;
    __syncthreads();
    for (int s = 128; s > 0; s >>= 1) {
        if (tid < s) red[tid] += red[tid + s];
        __syncthreads();
    }
    const float inv = 1.0f / red[0];
    __syncthreads();

    for (int i = tid; i < nv; i += 256) {
        float4 v = p[i];
        unsigned short h[4], l[4];
        split2(v.x * inv, h[0], l[0]);
        split2(v.y * inv, h[1], l[1]);
        split2(v.z * inv, h[2], l[2]);
        split2(v.w * inv, h[3], l[3]);
        size_t o = (size_t)row * n + i * 4;
        *reinterpret_cast<uint2*>(&phi[o]) = *reinterpret_cast<uint2*>(h);
        *reinterpret_cast<uint2*>(&plo[o]) = *reinterpret_cast<uint2*>(l);
    }
}

// ======================= launch ============================================
extern "C" void kernel_launch(void* const* d_in, const int* in_sizes, int n_in,
                              void* d_out, int out_size) {
    const float* x  = (const float*)d_in[0];
    const float* WQ = (const float*)d_in[1];
    const float* WK = (const float*)d_in[2];
    const float* WV = (const float*)d_in[3];
    const float* bQ = (const float*)d_in[4];
    const float* bK = (const float*)d_in[5];
    const float* bV = (const float*)d_in[6];
    float* out = (float*)d_out;

    float* S;
    unsigned short *xhi, *xlo, *wqhi, *wqlo, *wkhi, *wklo, *wvhi, *wvlo;
    unsigned short *qhi, *qlo, *khi, *klo, *vthi, *vtlo, *phi, *plo;
    cudaGetSymbolAddress((void**)&S, g_S);
    cudaGetSymbolAddress((void**)&xhi, g_xhi);   cudaGetSymbolAddress((void**)&xlo, g_xlo);
    cudaGetSymbolAddress((void**)&wqhi, g_wqhi); cudaGetSymbolAddress((void**)&wqlo, g_wqlo);
    cudaGetSymbolAddress((void**)&wkhi, g_wkhi); cudaGetSymbolAddress((void**)&wklo, g_wklo);
    cudaGetSymbolAddress((void**)&wvhi, g_wvhi); cudaGetSymbolAddress((void**)&wvlo, g_wvlo);
    cudaGetSymbolAddress((void**)&qhi, g_qhi);   cudaGetSymbolAddress((void**)&qlo, g_qlo);
    cudaGetSymbolAddress((void**)&khi, g_khi);   cudaGetSymbolAddress((void**)&klo, g_klo);
    cudaGetSymbolAddress((void**)&vthi, g_vthi); cudaGetSymbolAddress((void**)&vtlo, g_vtlo);
    cudaGetSymbolAddress((void**)&phi, g_phi);   cudaGetSymbolAddress((void**)&plo, g_plo);

    cudaFuncSetAttribute(gemm_mma<EPI_SPLIT, true>,
                         cudaFuncAttributeMaxDynamicSharedMemorySize, SMEM_DYN);
    cudaFuncSetAttribute(gemm_mma<EPI_SPLIT_T, true>,
                         cudaFuncAttributeMaxDynamicSharedMemorySize, SMEM_DYN);
    cudaFuncSetAttribute(gemm_mma<EPI_F32, false>,
                         cudaFuncAttributeMaxDynamicSharedMemorySize, SMEM_DYN);

    // split inputs
    split_kernel<<<(SEQ * DIM / 4 + 255) / 256, 256>>>(x, xhi, xlo, SEQ * DIM / 4);
    dim3 gT(DIM / 32, DIM / 32);
    splitT_kernel<<<gT, 256>>>(WQ, wqhi, wqlo, DIM, DIM);
    splitT_kernel<<<gT, 256>>>(WK, wkhi, wklo, DIM, DIM);
    splitT_kernel<<<gT, 256>>>(WV, wvhi, wvlo, DIM, DIM);

    // projections: [SEQ,DIM] = x @ W  (B = W^T, K-major)
    dim3 gProj(DIM / 128, SEQ / 128);
    gemm_mma<EPI_SPLIT, true><<<gProj, 256, SMEM_DYN>>>(
        xhi, xlo, wqhi, wqlo, bQ, nullptr, qhi, qlo, SEQ, DIM, DIM, 0, 1.0f);
    gemm_mma<EPI_SPLIT, true><<<gProj, 256, SMEM_DYN>>>(
        xhi, xlo, wkhi, wklo, bK, nullptr, khi, klo, SEQ, DIM, DIM, 0, 1.0f);
    gemm_mma<EPI_SPLIT_T, true><<<gProj, 256, SMEM_DYN>>>(
        xhi, xlo, wvhi, wvlo, bV, nullptr, vthi, vtlo, SEQ, DIM, DIM, SEQ, 1.0f);

    // scores: S = (Q @ K^T) / 32
    dim3 gScore(SEQ / 128, SEQ / 128);
    gemm_mma<EPI_F32, false><<<gScore, 256, SMEM_DYN>>>(
        qhi, qlo, khi, klo, nullptr, S, nullptr, nullptr,
        SEQ, SEQ, DIM, 0, 0.03125f);

    // softmax rows -> split probs
    softmax_split<<<SEQ, 256>>>(S, phi, plo, SEQ);

    // out = P @ V  (B = V^T, K-major over SEQ)
    dim3 gOut(DIM / 128, SEQ / 128);
    gemm_mma<EPI_F32, false><<<gOut, 256, SMEM_DYN>>>(
        phi, plo, vthi, vtlo, nullptr, out, nullptr, nullptr,
        SEQ, DIM, SEQ, 0, 1.0f);
}

// round 4
// speedup vs baseline: 2.5093x; 1.1155x over previous
#include <cuda_runtime.h>
#include <cuda_fp16.h>
#include <math.h>
#include <stdint.h>

#define SEQ 4096
#define DIM 1024

// ======================= device scratch (no cudaMalloc) ====================
__device__ float  g_S[(size_t)SEQ * SEQ];                    // scores fp32
__device__ __half g_xh[(size_t)SEQ * DIM],  g_xl[(size_t)SEQ * DIM];
__device__ __half g_wqh[(size_t)DIM * DIM], g_wql[(size_t)DIM * DIM];
__device__ __half g_wkh[(size_t)DIM * DIM], g_wkl[(size_t)DIM * DIM];
__device__ __half g_wvh[(size_t)DIM * DIM], g_wvl[(size_t)DIM * DIM];
__device__ __half g_qh[(size_t)SEQ * DIM],  g_ql[(size_t)SEQ * DIM];
__device__ __half g_kh[(size_t)SEQ * DIM],  g_kl[(size_t)SEQ * DIM];
__device__ __half g_vth[(size_t)DIM * SEQ], g_vtl[(size_t)DIM * SEQ]; // V^T
__device__ __half g_ph[(size_t)SEQ * SEQ];                            // probs fp16

// ======================= helpers ===========================================
__device__ __forceinline__ uint32_t smem_u32(const void* p) {
    uint32_t a;
    asm("{ .reg .u64 t; cvta.to.shared.u64 t, %1; cvt.u32.u64 %0, t; }"
        : "=r"(a) : "l"(p));
    return a;
}
__device__ __forceinline__ void cpasync16(uint32_t dst, const void* src) {
    asm volatile("cp.async.cg.shared.global [%0], [%1], 16;"
                 :: "r"(dst), "l"(src));
}
#define CP_COMMIT() asm volatile("cp.async.commit_group;" ::: "memory")
#define CP_WAIT(n)  asm volatile("cp.async.wait_group %0;" :: "n"(n) : "memory")

#define LDSM4(r0, r1, r2, r3, addr)                                          \
    asm volatile("ldmatrix.sync.aligned.m8n8.x4.shared.b16 {%0,%1,%2,%3}, [%4];" \
                 : "=r"(r0), "=r"(r1), "=r"(r2), "=r"(r3) : "r"(addr))

#define MMAF16(c, a0, a1, a2, a3, b0, b1)                                    \
    asm volatile("mma.sync.aligned.m16n8k16.row.col.f32.f16.f16.f32 "        \
                 "{%0,%1,%2,%3}, {%4,%5,%6,%7}, {%8,%9}, {%0,%1,%2,%3};"     \
                 : "+f"((c)[0]), "+f"((c)[1]), "+f"((c)[2]), "+f"((c)[3])    \
                 : "r"(a0), "r"(a1), "r"(a2), "r"(a3), "r"(b0), "r"(b1))

__device__ __forceinline__ void split2h(float v, __half& h, __half& l) {
    h = __float2half_rn(v);
    l = __float2half_rn(v - __half2float(h));
}

// ======================= GEMM: C[M,N] = alpha*(A @ B^T) + bias =============
// A [M,K] (fp16, optionally split A1+A2), B [N,K] fp16 split B1+B2, K-major.
// CTA tile 128 x BN, BK=32, 8 warps (2 x 4), warp tile 64 x (BN/4).
// TERMS=3: C = A1B1 + A1B2 + A2B1.   TERMS=2: C = A1B1 + A1B2 (A unsplit).
enum { EPI_F32 = 0, EPI_SPLIT = 1, EPI_SPLIT_T = 2 };

#define PITCH 80            // 32 fp16 (64B) + 16B pad per row

template <int BN, int TERMS, int EPI, bool BIAS>
__global__ __launch_bounds__(256, 1)
void gemm_mma(const __half* __restrict__ A1, const __half* __restrict__ A2,
              const __half* __restrict__ B1g, const __half* __restrict__ B2g,
              const float* __restrict__ bias,
              float* __restrict__ Cf, __half* __restrict__ Ch, __half* __restrict__ Cl,
              int M, int N, int K, int ldct, float alpha) {
    constexpr int WN = BN / 4;          // warp tile N: 32 or 64
    constexpr int NI = WN / 8;          // 4 or 8
    constexpr bool ASPL = (TERMS == 3);
    constexpr uint32_t A_SZ = 128 * PITCH;          // 10240
    constexpr uint32_t B_SZ = (uint32_t)BN * PITCH; // 10240 or 20480
    constexpr uint32_t OFF_B1 = (ASPL ? 2u : 1u) * A_SZ;
    constexpr uint32_t OFF_B2 = OFF_B1 + B_SZ;
    constexpr uint32_t STG = OFF_B2 + B_SZ;

    extern __shared__ char smem[];
    const uint32_t sb = smem_u32(smem);
    const int tid = threadIdx.x;
    const int lane = tid & 31;
    const int w = tid >> 5;
    const int wm = w >> 2;              // 0..1
    const int wn = w & 3;               // 0..3
    const int row0 = blockIdx.y * 128;
    const int col0 = blockIdx.x * BN;

    float acc[4][NI][4] = {};
    const int nk = K >> 5;

    // per-lane ldmatrix base offsets (bytes) — same mapping as validated R3
    const uint32_t aoff = ((lane & 7) + ((lane >> 3) & 1) * 8) * PITCH
                        + ((lane >> 4) & 1) * 16;
    const uint32_t boff = ((lane & 7) + ((lane >> 4) & 1) * 8) * PITCH
                        + ((lane >> 3) & 1) * 16;

    auto load_stage = [&](int slot, int kt) {
        uint32_t s0 = sb + (uint32_t)slot * STG;
        int k0 = kt << 5;
#pragma unroll
        for (int p = 0; p < 2; p++) {
            int idx = tid + p * 256;
            int r = idx >> 2, c = idx & 3;
            uint32_t d = s0 + r * PITCH + c * 16;
            size_t g = (size_t)(row0 + r) * K + k0 + c * 8;
            cpasync16(d, A1 + g);
            if (ASPL) cpasync16(d + A_SZ, A2 + g);
        }
#pragma unroll
        for (int p = 0; p < BN / 64; p++) {
            int idx = tid + p * 256;
            int r = idx >> 2, c = idx & 3;
            uint32_t d = s0 + OFF_B1 + r * PITCH + c * 16;
            size_t g = (size_t)(col0 + r) * K + k0 + c * 8;
            cpasync16(d, B1g + g);
            cpasync16(d + B_SZ, B2g + g);
        }
    };

    load_stage(0, 0);
    CP_COMMIT();
    load_stage(1, 1);
    CP_COMMIT();

    int slot = 0;
    for (int kt = 0; kt < nk; kt++) {
        CP_WAIT(1);
        __syncthreads();
        if (kt + 2 < nk) {
            int ns = slot + 2; if (ns >= 3) ns -= 3;
            load_stage(ns, kt + 2);
        }
        CP_COMMIT();

        const uint32_t s0 = sb + (uint32_t)slot * STG;
        const uint32_t aB = s0 + (wm * 64) * PITCH + aoff;
        const uint32_t bB = s0 + OFF_B1 + (wn * WN) * PITCH + boff;
#pragma unroll
        for (int ks = 0; ks < 2; ks++) {
            uint32_t a1[4][4], a2[4][4];
#pragma unroll
            for (int mi = 0; mi < 4; mi++) {
                uint32_t a = aB + mi * (16 * PITCH) + ks * 32;
                LDSM4(a1[mi][0], a1[mi][1], a1[mi][2], a1[mi][3], a);
                if (ASPL) LDSM4(a2[mi][0], a2[mi][1], a2[mi][2], a2[mi][3], a + A_SZ);
            }
            uint32_t b1[NI][2], b2[NI][2];
#pragma unroll
            for (int j = 0; j < NI / 2; j++) {
                uint32_t b = bB + j * (16 * PITCH) + ks * 32;
                LDSM4(b1[2 * j][0], b1[2 * j][1], b1[2 * j + 1][0], b1[2 * j + 1][1], b);
                LDSM4(b2[2 * j][0], b2[2 * j][1], b2[2 * j + 1][0], b2[2 * j + 1][1],
                      b + B_SZ);
            }
#pragma unroll
            for (int mi = 0; mi < 4; mi++)
#pragma unroll
                for (int ni = 0; ni < NI; ni++) {
                    MMAF16(acc[mi][ni], a1[mi][0], a1[mi][1], a1[mi][2], a1[mi][3],
                           b1[ni][0], b1[ni][1]);
                    MMAF16(acc[mi][ni], a1[mi][0], a1[mi][1], a1[mi][2], a1[mi][3],
                           b2[ni][0], b2[ni][1]);
                    if (ASPL)
                        MMAF16(acc[mi][ni], a2[mi][0], a2[mi][1], a2[mi][2], a2[mi][3],
                               b1[ni][0], b1[ni][1]);
                }
        }
        slot++; if (slot >= 3) slot = 0;
    }

    CP_WAIT(0);
    __syncthreads();

    const int tr = lane >> 2;          // 0..7
    const int tc = (lane & 3) * 2;     // 0,2,4,6

    if (EPI == EPI_SPLIT_T) {
        // stage fp32 tile in smem, then transposed coalesced split stores
        float* T = reinterpret_cast<float*>(smem);   // [128][133]
#pragma unroll
        for (int mi = 0; mi < 4; mi++)
#pragma unroll
            for (int ni = 0; ni < NI; ni++) {
                int r = wm * 64 + mi * 16 + tr;
                int c = wn * WN + ni * 8 + tc;
                T[r * 133 + c]           = acc[mi][ni][0];
                T[r * 133 + c + 1]       = acc[mi][ni][1];
                T[(r + 8) * 133 + c]     = acc[mi][ni][2];
                T[(r + 8) * 133 + c + 1] = acc[mi][ni][3];
            }
        __syncthreads();
        const int m = tid & 127;
        const int half = tid >> 7;
#pragma unroll 1
        for (int n = half; n < BN; n += 2) {
            float v = T[m * 133 + n] * alpha;
            if (BIAS) v += bias[col0 + n];
            __half h, l;
            split2h(v, h, l);
            size_t o = (size_t)(col0 + n) * ldct + row0 + m;
            Ch[o] = h;
            Cl[o] = l;
        }
    } else {
#pragma unroll
        for (int mi = 0; mi < 4; mi++)
#pragma unroll
            for (int ni = 0; ni < NI; ni++) {
                int r = row0 + wm * 64 + mi * 16 + tr;
                int c = col0 + wn * WN + ni * 8 + tc;
#pragma unroll
                for (int hh = 0; hh < 2; hh++) {
                    int rr = r + hh * 8;
                    float v0 = acc[mi][ni][2 * hh + 0] * alpha;
                    float v1 = acc[mi][ni][2 * hh + 1] * alpha;
                    if (BIAS) { v0 += bias[c]; v1 += bias[c + 1]; }
                    if (EPI == EPI_F32) {
                        float2 f2 = make_float2(v0, v1);
                        *reinterpret_cast<float2*>(&Cf[(size_t)rr * N + c]) = f2;
                    } else {
                        __half h0, l0, h1, l1;
                        split2h(v0, h0, l0);
                        split2h(v1, h1, l1);
                        __half2 hp = __halves2half2(h0, h1);
                        __half2 lp = __halves2half2(l0, l1);
                        *reinterpret_cast<__half2*>(&Ch[(size_t)rr * N + c]) = hp;
                        *reinterpret_cast<__half2*>(&Cl[(size_t)rr * N + c]) = lp;
                    }
                }
            }
    }
}

// ======================= elementwise split (x) =============================
__global__ __launch_bounds__(256)
void split_kernel(const float* __restrict__ in, __half* __restrict__ hi,
                  __half* __restrict__ lo, int n4) {
    int i = blockIdx.x * 256 + threadIdx.x;
    if (i >= n4) return;
    float4 v = reinterpret_cast<const float4*>(in)[i];
    __half h[4], l[4];
    split2h(v.x, h[0], l[0]);
    split2h(v.y, h[1], l[1]);
    split2h(v.z, h[2], l[2]);
    split2h(v.w, h[3], l[3]);
    reinterpret_cast<uint2*>(hi)[i] = *reinterpret_cast<uint2*>(h);
    reinterpret_cast<uint2*>(lo)[i] = *reinterpret_cast<uint2*>(l);
}

// ======================= split + transpose (W -> W^T) ======================
__global__ __launch_bounds__(256)
void splitT_kernel(const float* __restrict__ in, __half* __restrict__ hiT,
                   __half* __restrict__ loT, int R, int C) {
    __shared__ float t[32][33];
    const int tx = threadIdx.x & 31, ty = threadIdx.x >> 5;
    const int bc = blockIdx.x * 32, br = blockIdx.y * 32;
#pragma unroll
    for (int j = 0; j < 4; j++)
        t[ty + 8 * j][tx] = in[(size_t)(br + ty + 8 * j) * C + bc + tx];
    __syncthreads();
#pragma unroll
    for (int j = 0; j < 4; j++) {
        int cc = ty + 8 * j;
        __half h, l;
        split2h(t[tx][cc], h, l);
        hiT[(size_t)(bc + cc) * R + br + tx] = h;
        loT[(size_t)(bc + cc) * R + br + tx] = l;
    }
}

// ======================= softmax rows -> fp16 probs ========================
__global__ __launch_bounds__(256)
void softmax_h(const float* __restrict__ S, __half* __restrict__ ph, int n) {
    const int row = blockIdx.x;
    const float4* p = reinterpret_cast<const float4*>(S + (size_t)row * n);
    const int nv = n / 4;
    const int tid = threadIdx.x;
    __shared__ float red[256];

    float m = -INFINITY;
    for (int i = tid; i < nv; i += 256) {
        float4 v = p[i];
        m = fmaxf(m, fmaxf(fmaxf(v.x, v.y), fmaxf(v.z, v.w)));
    }
    red[tid] = m;
    __syncthreads();
    for (int s = 128; s > 0; s >>= 1) {
        if (tid < s) red[tid] = fmaxf(red[tid], red[tid + s]);
        __syncthreads();
    }
    m = red[0];
    __syncthreads();

    float sum = 0.0f;
    for (int i = tid; i < nv; i += 256) {
        float4 v = p[i];
        sum += (expf(v.x - m) + expf(v.y - m)) + (expf(v.z - m) + expf(v.w - m));
    }
    red[tid] = sum;
    __syncthreads();
    for (int s = 128; s > 0; s >>= 1) {
        if (tid < s) red[tid] += red[tid + s];
        __syncthreads();
    }
    const float inv = 1.0f / red[0];
    __syncthreads();

    for (int i = tid; i < nv; i += 256) {
        float4 v = p[i];
        __half h[4];
        h[0] = __float2half_rn(expf(v.x - m) * inv);
        h[1] = __float2half_rn(expf(v.y - m) * inv);
        h[2] = __float2half_rn(expf(v.z - m) * inv);
        h[3] = __float2half_rn(expf(v.w - m) * inv);
        reinterpret_cast<uint2*>(ph + (size_t)row * n)[i] =
            *reinterpret_cast<uint2*>(h);
    }
}

// ======================= launch ============================================
extern "C" void kernel_launch(void* const* d_in, const int* in_sizes, int n_in,
                              void* d_out, int out_size) {
    const float* x  = (const float*)d_in[0];
    const float* WQ = (const float*)d_in[1];
    const float* WK = (const float*)d_in[2];
    const float* WV = (const float*)d_in[3];
    const float* bQ = (const float*)d_in[4];
    const float* bK = (const float*)d_in[5];
    const float* bV = (const float*)d_in[6];
    float* out = (float*)d_out;

    float* S;
    __half *xh, *xl, *wqh, *wql, *wkh, *wkl, *wvh, *wvl;
    __half *qh, *ql, *kh, *kl, *vth, *vtl, *ph;
    cudaGetSymbolAddress((void**)&S, g_S);
    cudaGetSymbolAddress((void**)&xh, g_xh);   cudaGetSymbolAddress((void**)&xl, g_xl);
    cudaGetSymbolAddress((void**)&wqh, g_wqh); cudaGetSymbolAddress((void**)&wql, g_wql);
    cudaGetSymbolAddress((void**)&wkh, g_wkh); cudaGetSymbolAddress((void**)&wkl, g_wkl);
    cudaGetSymbolAddress((void**)&wvh, g_wvh); cudaGetSymbolAddress((void**)&wvl, g_wvl);
    cudaGetSymbolAddress((void**)&qh, g_qh);   cudaGetSymbolAddress((void**)&ql, g_ql);
    cudaGetSymbolAddress((void**)&kh, g_kh);   cudaGetSymbolAddress((void**)&kl, g_kl);
    cudaGetSymbolAddress((void**)&vth, g_vth); cudaGetSymbolAddress((void**)&vtl, g_vtl);
    cudaGetSymbolAddress((void**)&ph, g_ph);

    // smem per instantiation: stage = (ASPL?2:1)*10240 + 2*BN*80, x3 stages
    constexpr int SM_P  = 3 * (2 * 10240 + 2 * 10240);  // 122880 proj (BN=128,T=3)
    constexpr int SM_SC = 3 * (2 * 10240 + 2 * 20480);  // 184320 scores(BN=256,T=3)
    constexpr int SM_PV = 3 * (1 * 10240 + 2 * 10240);  //  92160 pv   (BN=128,T=2)

    cudaFuncSetAttribute((const void*)gemm_mma<128, 3, EPI_SPLIT, true>,
                         cudaFuncAttributeMaxDynamicSharedMemorySize, SM_P);
    cudaFuncSetAttribute((const void*)gemm_mma<128, 3, EPI_SPLIT_T, true>,
                         cudaFuncAttributeMaxDynamicSharedMemorySize, SM_P);
    cudaFuncSetAttribute((const void*)gemm_mma<256, 3, EPI_F32, false>,
                         cudaFuncAttributeMaxDynamicSharedMemorySize, SM_SC);
    cudaFuncSetAttribute((const void*)gemm_mma<128, 2, EPI_F32, false>,
                         cudaFuncAttributeMaxDynamicSharedMemorySize, SM_PV);

    // split inputs
    split_kernel<<<(SEQ * DIM / 4 + 255) / 256, 256>>>(x, xh, xl, SEQ * DIM / 4);
    dim3 gT(DIM / 32, DIM / 32);
    splitT_kernel<<<gT, 256>>>(WQ, wqh, wql, DIM, DIM);
    splitT_kernel<<<gT, 256>>>(WK, wkh, wkl, DIM, DIM);
    splitT_kernel<<<gT, 256>>>(WV, wvh, wvl, DIM, DIM);

    // projections: [SEQ,DIM] = x @ W  (B = W^T, K-major)
    dim3 gProj(DIM / 128, SEQ / 128);
    gemm_mma<128, 3, EPI_SPLIT, true><<<gProj, 256, SM_P>>>(
        xh, xl, wqh, wql, bQ, nullptr, qh, ql, SEQ, DIM, DIM, 0, 1.0f);
    gemm_mma<128, 3, EPI_SPLIT, true><<<gProj, 256, SM_P>>>(
        xh, xl, wkh, wkl, bK, nullptr, kh, kl, SEQ, DIM, DIM, 0, 1.0f);
    gemm_mma<128, 3, EPI_SPLIT_T, true><<<gProj, 256, SM_P>>>(
        xh, xl, wvh, wvl, bV, nullptr, vth, vtl, SEQ, DIM, DIM, SEQ, 1.0f);

    // scores: S = (Q @ K^T) / 32   (BN=256 tile)
    dim3 gScore(SEQ / 256, SEQ / 128);
    gemm_mma<256, 3, EPI_F32, false><<<gScore, 256, SM_SC>>>(
        qh, ql, kh, kl, nullptr, S, nullptr, nullptr,
        SEQ, SEQ, DIM, 0, 0.03125f);

    // softmax rows -> single fp16 probs
    softmax_h<<<SEQ, 256>>>(S, ph, SEQ);

    // out = P @ V  (A = P single fp16, B = V^T split; TERMS=2)
    dim3 gOut(DIM / 128, SEQ / 128);
    gemm_mma<128, 2, EPI_F32, false><<<gOut, 256, SM_PV>>>(
        ph, nullptr, vth, vtl, nullptr, out, nullptr, nullptr,
        SEQ, DIM, SEQ, 0, 1.0f);
}

// round 5
// speedup vs baseline: 3.2949x; 1.3131x over previous
#include <cuda_runtime.h>
#include <cuda_fp16.h>
#include <math.h>
#include <stdint.h>

#define SEQ 4096
#define DIM 1024

// ======================= device scratch (no cudaMalloc) ====================
__device__ float  g_S[(size_t)SEQ * SEQ];                    // scores fp32
__device__ __half g_xh[(size_t)SEQ * DIM],  g_xl[(size_t)SEQ * DIM];
__device__ __half g_wqh[(size_t)DIM * DIM], g_wql[(size_t)DIM * DIM];
__device__ __half g_wkh[(size_t)DIM * DIM], g_wkl[(size_t)DIM * DIM];
__device__ __half g_wvh[(size_t)DIM * DIM], g_wvl[(size_t)DIM * DIM];
__device__ __half g_qh[(size_t)SEQ * DIM],  g_ql[(size_t)SEQ * DIM];
__device__ __half g_kh[(size_t)SEQ * DIM],  g_kl[(size_t)SEQ * DIM];
__device__ __half g_vth[(size_t)DIM * SEQ], g_vtl[(size_t)DIM * SEQ]; // V^T
__device__ __half g_ph[(size_t)SEQ * SEQ];                            // probs fp16

// ======================= helpers ===========================================
__device__ __forceinline__ uint32_t smem_u32(const void* p) {
    uint32_t a;
    asm("{ .reg .u64 t; cvta.to.shared.u64 t, %1; cvt.u32.u64 %0, t; }"
        : "=r"(a) : "l"(p));
    return a;
}
__device__ __forceinline__ void cpasync16(uint32_t dst, const void* src) {
    asm volatile("cp.async.cg.shared.global [%0], [%1], 16;"
                 :: "r"(dst), "l"(src));
}
#define CP_COMMIT() asm volatile("cp.async.commit_group;" ::: "memory")
#define CP_WAIT(n)  asm volatile("cp.async.wait_group %0;" :: "n"(n) : "memory")

#define LDSM4(r0, r1, r2, r3, addr)                                          \
    asm volatile("ldmatrix.sync.aligned.m8n8.x4.shared.b16 {%0,%1,%2,%3}, [%4];" \
                 : "=r"(r0), "=r"(r1), "=r"(r2), "=r"(r3) : "r"(addr))

#define MMAF16(c, a0, a1, a2, a3, b0, b1)                                    \
    asm volatile("mma.sync.aligned.m16n8k16.row.col.f32.f16.f16.f32 "        \
                 "{%0,%1,%2,%3}, {%4,%5,%6,%7}, {%8,%9}, {%0,%1,%2,%3};"     \
                 : "+f"((c)[0]), "+f"((c)[1]), "+f"((c)[2]), "+f"((c)[3])    \
                 : "r"(a0), "r"(a1), "r"(a2), "r"(a3), "r"(b0), "r"(b1))

__device__ __forceinline__ void split2h(float v, __half& h, __half& l) {
    h = __float2half_rn(v);
    l = __float2half_rn(v - __half2float(h));
}

// ======================= GEMM: C[M,N] = alpha*(A @ B^T) + bias =============
// A [M,K] fp16 (split A1+A2 when TERMS=3), B [N,K] fp16 split B1+B2, K-major.
// CTA tile 128x128, BK=32, 8 warps (2x4), warp tile 64x32. SW64-swizzled
// smem, 64B pitch, 3-stage cp.async pipeline, 2 CTAs/SM.
enum { EPI_F32 = 0, EPI_SPLIT = 1, EPI_SPLIT_T = 2 };

struct GArgs {
    const __half* A1;
    const __half* A2;
    const __half* B1[3];
    const __half* B2[3];
    const float*  bias[3];
    float*        Cf;
    __half*       Ch[3];
    __half*       Cl[3];
    int           epi[3];
    int M, N, K, ldct;
    float alpha;
};

// swizzled byte offset inside an 8KB (128 rows x 64B) region
__device__ __forceinline__ uint32_t sw64(uint32_t r, uint32_t c16) {
    return r * 64 + (((c16 ^ ((r >> 1) & 3)) & 3) << 4);
}

template <int TERMS>
__global__ __launch_bounds__(256, 2)
void gemm_mma(const GArgs ga) {
    constexpr bool ASPL = (TERMS == 3);
    constexpr uint32_t R_SZ = 8192;                 // one matrix region
    constexpr uint32_t OFF_A2 = R_SZ;               // (3-term only)
    constexpr uint32_t OFF_B1 = ASPL ? 2 * R_SZ : R_SZ;
    constexpr uint32_t OFF_B2 = OFF_B1 + R_SZ;
    constexpr uint32_t STG = OFF_B2 + R_SZ;         // 32768 or 24576

    extern __shared__ char smem[];
    const uint32_t sb = smem_u32(smem);
    const int tid = threadIdx.x;
    const int lane = tid & 31;
    const int w = tid >> 5;
    const int wm = w >> 2;              // 0..1
    const int wn = w & 3;               // 0..3
    const int z = blockIdx.z;
    const int row0 = blockIdx.y * 128;
    const int col0 = blockIdx.x * 128;

    const __half* __restrict__ A1 = ga.A1;
    const __half* __restrict__ A2 = ga.A2;
    const __half* __restrict__ B1g = ga.B1[z];
    const __half* __restrict__ B2g = ga.B2[z];
    const int K = ga.K;

    float acc[4][4][4] = {};
    const int nk = K >> 5;

    auto load_stage = [&](int slot, int kt) {
        uint32_t s0 = sb + (uint32_t)slot * STG;
        int k0 = kt << 5;
#pragma unroll
        for (int p = 0; p < 2; p++) {
            int idx = tid + p * 256;
            uint32_t r = idx >> 2, c = idx & 3;
            uint32_t d = s0 + sw64(r, c);
            size_t gA = (size_t)(row0 + r) * K + k0 + c * 8;
            size_t gB = (size_t)(col0 + r) * K + k0 + c * 8;
            cpasync16(d, A1 + gA);
            if (ASPL) cpasync16(d + OFF_A2, A2 + gA);
            cpasync16(d + OFF_B1, B1g + gB);
            cpasync16(d + OFF_B2, B2g + gB);
        }
    };

    // per-lane ldmatrix swizzled base offsets (bytes within region)
    const uint32_t r0a = (lane & 7) + ((lane >> 3) & 1) * 8 + wm * 64;
    const uint32_t swa = ((r0a >> 1) & 3) << 4;
    const uint32_t aoff = r0a * 64 + ((((lane >> 4) & 1) << 4) ^ swa);
    const uint32_t r0b = (lane & 7) + ((lane >> 4) & 1) * 8 + wn * 32;
    const uint32_t swb = ((r0b >> 1) & 3) << 4;
    const uint32_t boff = r0b * 64 + ((((lane >> 3) & 1) << 4) ^ swb);

    load_stage(0, 0);
    CP_COMMIT();
    load_stage(1, 1);
    CP_COMMIT();

    int slot = 0;
    for (int kt = 0; kt < nk; kt++) {
        CP_WAIT(1);
        __syncthreads();
        if (kt + 2 < nk) {
            int ns = slot + 2; if (ns >= 3) ns -= 3;
            load_stage(ns, kt + 2);
        }
        CP_COMMIT();

        const uint32_t s0 = sb + (uint32_t)slot * STG;
        const uint32_t aB = s0 + aoff;
        const uint32_t bB = s0 + OFF_B1 + boff;
#pragma unroll
        for (int ks = 0; ks < 2; ks++) {
            uint32_t a1[4][4], a2[4][4];
#pragma unroll
            for (int mi = 0; mi < 4; mi++) {
                uint32_t a = (aB + mi * 1024) ^ (ks << 5);
                LDSM4(a1[mi][0], a1[mi][1], a1[mi][2], a1[mi][3], a);
                if (ASPL) LDSM4(a2[mi][0], a2[mi][1], a2[mi][2], a2[mi][3],
                                a + OFF_A2);
            }
            uint32_t b1[4][2], b2[4][2];
#pragma unroll
            for (int j = 0; j < 2; j++) {
                uint32_t b = (bB + j * 1024) ^ (ks << 5);
                LDSM4(b1[2 * j][0], b1[2 * j][1], b1[2 * j + 1][0],
                      b1[2 * j + 1][1], b);
                LDSM4(b2[2 * j][0], b2[2 * j][1], b2[2 * j + 1][0],
                      b2[2 * j + 1][1], b + R_SZ);
            }
#pragma unroll
            for (int mi = 0; mi < 4; mi++)
#pragma unroll
                for (int ni = 0; ni < 4; ni++) {
                    MMAF16(acc[mi][ni], a1[mi][0], a1[mi][1], a1[mi][2], a1[mi][3],
                           b1[ni][0], b1[ni][1]);
                    MMAF16(acc[mi][ni], a1[mi][0], a1[mi][1], a1[mi][2], a1[mi][3],
                           b2[ni][0], b2[ni][1]);
                    if (ASPL)
                        MMAF16(acc[mi][ni], a2[mi][0], a2[mi][1], a2[mi][2], a2[mi][3],
                               b1[ni][0], b1[ni][1]);
                }
        }
        slot++; if (slot >= 3) slot = 0;
    }

    CP_WAIT(0);
    __syncthreads();

    const int tr = lane >> 2;          // 0..7
    const int tc = (lane & 3) * 2;     // 0,2,4,6
    const int epi = ga.epi[z];
    const float* bias = ga.bias[z];
    const float alpha = ga.alpha;

    if (epi == EPI_SPLIT_T) {
        __half* __restrict__ Ch = ga.Ch[z];
        __half* __restrict__ Cl = ga.Cl[z];
        float* T = reinterpret_cast<float*>(smem);   // [128][133] = 68KB
#pragma unroll
        for (int mi = 0; mi < 4; mi++)
#pragma unroll
            for (int ni = 0; ni < 4; ni++) {
                int r = wm * 64 + mi * 16 + tr;
                int c = wn * 32 + ni * 8 + tc;
                T[r * 133 + c]           = acc[mi][ni][0];
                T[r * 133 + c + 1]       = acc[mi][ni][1];
                T[(r + 8) * 133 + c]     = acc[mi][ni][2];
                T[(r + 8) * 133 + c + 1] = acc[mi][ni][3];
            }
        __syncthreads();
        const int m = tid & 127;
        const int half = tid >> 7;
#pragma unroll 1
        for (int n = half; n < 128; n += 2) {
            float v = T[m * 133 + n] * alpha + bias[col0 + n];
            __half h, l;
            split2h(v, h, l);
            size_t o = (size_t)(col0 + n) * ga.ldct + row0 + m;
            Ch[o] = h;
            Cl[o] = l;
        }
    } else if (epi == EPI_SPLIT) {
        __half* __restrict__ Ch = ga.Ch[z];
        __half* __restrict__ Cl = ga.Cl[z];
        const int N = ga.N;
#pragma unroll
        for (int mi = 0; mi < 4; mi++)
#pragma unroll
            for (int ni = 0; ni < 4; ni++) {
                int r = row0 + wm * 64 + mi * 16 + tr;
                int c = col0 + wn * 32 + ni * 8 + tc;
#pragma unroll
                for (int hh = 0; hh < 2; hh++) {
                    int rr = r + hh * 8;
                    float v0 = acc[mi][ni][2 * hh + 0] * alpha + bias[c];
                    float v1 = acc[mi][ni][2 * hh + 1] * alpha + bias[c + 1];
                    __half h0, l0, h1, l1;
                    split2h(v0, h0, l0);
                    split2h(v1, h1, l1);
                    *reinterpret_cast<__half2*>(&Ch[(size_t)rr * N + c]) =
                        __halves2half2(h0, h1);
                    *reinterpret_cast<__half2*>(&Cl[(size_t)rr * N + c]) =
                        __halves2half2(l0, l1);
                }
            }
    } else {  // EPI_F32
        float* __restrict__ Cf = ga.Cf;
        const int N = ga.N;
#pragma unroll
        for (int mi = 0; mi < 4; mi++)
#pragma unroll
            for (int ni = 0; ni < 4; ni++) {
                int r = row0 + wm * 64 + mi * 16 + tr;
                int c = col0 + wn * 32 + ni * 8 + tc;
#pragma unroll
                for (int hh = 0; hh < 2; hh++) {
                    int rr = r + hh * 8;
                    float2 f2 = make_float2(acc[mi][ni][2 * hh + 0] * alpha,
                                            acc[mi][ni][2 * hh + 1] * alpha);
                    *reinterpret_cast<float2*>(&Cf[(size_t)rr * N + c]) = f2;
                }
            }
    }
}

// ======================= elementwise split (x) =============================
__global__ __launch_bounds__(256)
void split_kernel(const float* __restrict__ in, __half* __restrict__ hi,
                  __half* __restrict__ lo, int n4) {
    int i = blockIdx.x * 256 + threadIdx.x;
    if (i >= n4) return;
    float4 v = reinterpret_cast<const float4*>(in)[i];
    __half h[4], l[4];
    split2h(v.x, h[0], l[0]);
    split2h(v.y, h[1], l[1]);
    split2h(v.z, h[2], l[2]);
    split2h(v.w, h[3], l[3]);
    reinterpret_cast<uint2*>(hi)[i] = *reinterpret_cast<uint2*>(h);
    reinterpret_cast<uint2*>(lo)[i] = *reinterpret_cast<uint2*>(l);
}

// ======================= split + transpose (W -> W^T) ======================
__global__ __launch_bounds__(256)
void splitT_kernel(const float* __restrict__ in, __half* __restrict__ hiT,
                   __half* __restrict__ loT, int R, int C) {
    __shared__ float t[32][33];
    const int tx = threadIdx.x & 31, ty = threadIdx.x >> 5;
    const int bc = blockIdx.x * 32, br = blockIdx.y * 32;
#pragma unroll
    for (int j = 0; j < 4; j++)
        t[ty + 8 * j][tx] = in[(size_t)(br + ty + 8 * j) * C + bc + tx];
    __syncthreads();
#pragma unroll
    for (int j = 0; j < 4; j++) {
        int cc = ty + 8 * j;
        __half h, l;
        split2h(t[tx][cc], h, l);
        hiT[(size_t)(bc + cc) * R + br + tx] = h;
        loT[(size_t)(bc + cc) * R + br + tx] = l;
    }
}

// ======================= softmax rows -> fp16 probs ========================
__global__ __launch_bounds__(256)
void softmax_h(const float* __restrict__ S, __half* __restrict__ ph, int n) {
    const int row = blockIdx.x;
    const float4* p = reinterpret_cast<const float4*>(S + (size_t)row * n);
    const int nv = n / 4;
    const int tid = threadIdx.x;
    __shared__ float red[256];

    float m = -INFINITY;
    for (int i = tid; i < nv; i += 256) {
        float4 v = p[i];
        m = fmaxf(m, fmaxf(fmaxf(v.x, v.y), fmaxf(v.z, v.w)));
    }
    red[tid] = m;
    __syncthreads();
    for (int s = 128; s > 0; s >>= 1) {
        if (tid < s) red[tid] = fmaxf(red[tid], red[tid + s]);
        __syncthreads();
    }
    m = red[0];
    __syncthreads();

    float sum = 0.0f;
    for (int i = tid; i < nv; i += 256) {
        float4 v = p[i];
        sum += (expf(v.x - m) + expf(v.y - m)) + (expf(v.z - m) + expf(v.w - m));
    }
    red[tid] = sum;
    __syncthreads();
    for (int s = 128; s > 0; s >>= 1) {
        if (tid < s) red[tid] += red[tid + s];
        __syncthreads();
    }
    const float inv = 1.0f / red[0];
    __syncthreads();

    for (int i = tid; i < nv; i += 256) {
        float4 v = p[i];
        __half h[4];
        h[0] = __float2half_rn(expf(v.x - m) * inv);
        h[1] = __float2half_rn(expf(v.y - m) * inv);
        h[2] = __float2half_rn(expf(v.z - m) * inv);
        h[3] = __float2half_rn(expf(v.w - m) * inv);
        reinterpret_cast<uint2*>(ph + (size_t)row * n)[i] =
            *reinterpret_cast<uint2*>(h);
    }
}

// ======================= launch ============================================
extern "C" void kernel_launch(void* const* d_in, const int* in_sizes, int n_in,
                              void* d_out, int out_size) {
    const float* x  = (const float*)d_in[0];
    const float* WQ = (const float*)d_in[1];
    const float* WK = (const float*)d_in[2];
    const float* WV = (const float*)d_in[3];
    const float* bQ = (const float*)d_in[4];
    const float* bK = (const float*)d_in[5];
    const float* bV = (const float*)d_in[6];
    float* out = (float*)d_out;

    float* S;
    __half *xh, *xl, *wqh, *wql, *wkh, *wkl, *wvh, *wvl;
    __half *qh, *ql, *kh, *kl, *vth, *vtl, *ph;
    cudaGetSymbolAddress((void**)&S, g_S);
    cudaGetSymbolAddress((void**)&xh, g_xh);   cudaGetSymbolAddress((void**)&xl, g_xl);
    cudaGetSymbolAddress((void**)&wqh, g_wqh); cudaGetSymbolAddress((void**)&wql, g_wql);
    cudaGetSymbolAddress((void**)&wkh, g_wkh); cudaGetSymbolAddress((void**)&wkl, g_wkl);
    cudaGetSymbolAddress((void**)&wvh, g_wvh); cudaGetSymbolAddress((void**)&wvl, g_wvl);
    cudaGetSymbolAddress((void**)&qh, g_qh);   cudaGetSymbolAddress((void**)&ql, g_ql);
    cudaGetSymbolAddress((void**)&kh, g_kh);   cudaGetSymbolAddress((void**)&kl, g_kl);
    cudaGetSymbolAddress((void**)&vth, g_vth); cudaGetSymbolAddress((void**)&vtl, g_vtl);
    cudaGetSymbolAddress((void**)&ph, g_ph);

    constexpr int SM_3T = 3 * 32768;   // 98304 per CTA -> 2 CTAs/SM
    constexpr int SM_2T = 3 * 24576;   // 73728 per CTA -> 2 CTAs/SM

    cudaFuncSetAttribute((const void*)gemm_mma<3>,
                         cudaFuncAttributeMaxDynamicSharedMemorySize, SM_3T);
    cudaFuncSetAttribute((const void*)gemm_mma<2>,
                         cudaFuncAttributeMaxDynamicSharedMemorySize, SM_2T);

    // split inputs
    split_kernel<<<(SEQ * DIM / 4 + 255) / 256, 256>>>(x, xh, xl, SEQ * DIM / 4);
    dim3 gT(DIM / 32, DIM / 32);
    splitT_kernel<<<gT, 256>>>(WQ, wqh, wql, DIM, DIM);
    splitT_kernel<<<gT, 256>>>(WK, wkh, wkl, DIM, DIM);
    splitT_kernel<<<gT, 256>>>(WV, wvh, wvl, DIM, DIM);

    // fused QKV projections: z=0 -> Q, z=1 -> K, z=2 -> V^T
    {
        GArgs ga = {};
        ga.A1 = xh; ga.A2 = xl;
        ga.B1[0] = wqh; ga.B1[1] = wkh; ga.B1[2] = wvh;
        ga.B2[0] = wql; ga.B2[1] = wkl; ga.B2[2] = wvl;
        ga.bias[0] = bQ; ga.bias[1] = bK; ga.bias[2] = bV;
        ga.Ch[0] = qh; ga.Ch[1] = kh; ga.Ch[2] = vth;
        ga.Cl[0] = ql; ga.Cl[1] = kl; ga.Cl[2] = vtl;
        ga.epi[0] = EPI_SPLIT; ga.epi[1] = EPI_SPLIT; ga.epi[2] = EPI_SPLIT_T;
        ga.M = SEQ; ga.N = DIM; ga.K = DIM; ga.ldct = SEQ; ga.alpha = 1.0f;
        dim3 g(DIM / 128, SEQ / 128, 3);
        gemm_mma<3><<<g, 256, SM_3T>>>(ga);
    }

    // scores: S = (Q @ K^T) / 32
    {
        GArgs ga = {};
        ga.A1 = qh; ga.A2 = ql;
        ga.B1[0] = kh; ga.B2[0] = kl;
        ga.Cf = S;
        ga.epi[0] = EPI_F32;
        ga.M = SEQ; ga.N = SEQ; ga.K = DIM; ga.ldct = 0; ga.alpha = 0.03125f;
        dim3 g(SEQ / 128, SEQ / 128, 1);
        gemm_mma<3><<<g, 256, SM_3T>>>(ga);
    }

    // softmax rows -> single fp16 probs
    softmax_h<<<SEQ, 256>>>(S, ph, SEQ);

    // out = P @ V  (A = P single fp16, B = V^T split; TERMS=2)
    {
        GArgs ga = {};
        ga.A1 = ph; ga.A2 = nullptr;
        ga.B1[0] = vth; ga.B2[0] = vtl;
        ga.Cf = out;
        ga.epi[0] = EPI_F32;
        ga.M = SEQ; ga.N = DIM; ga.K = SEQ; ga.ldct = 0; ga.alpha = 1.0f;
        dim3 g(DIM / 128, SEQ / 128, 1);
        gemm_mma<2><<<g, 256, SM_2T>>>(ga);
    }
}

// round 6
// speedup vs baseline: 3.7251x; 1.1306x over previous
#include <cuda_runtime.h>
#include <cuda_fp16.h>
#include <math.h>
#include <stdint.h>

#define SEQ 4096
#define DIM 1024

// ======================= device scratch (no cudaMalloc) ====================
__device__ float  g_S[(size_t)SEQ * SEQ];                    // scores fp32
__device__ __half g_xh[(size_t)SEQ * DIM],  g_xl[(size_t)SEQ * DIM];
__device__ __half g_wqh[(size_t)DIM * DIM], g_wql[(size_t)DIM * DIM];
__device__ __half g_wkh[(size_t)DIM * DIM], g_wkl[(size_t)DIM * DIM];
__device__ __half g_wvh[(size_t)DIM * DIM], g_wvl[(size_t)DIM * DIM];
__device__ __half g_qh[(size_t)SEQ * DIM],  g_ql[(size_t)SEQ * DIM];
__device__ __half g_kh[(size_t)SEQ * DIM],  g_kl[(size_t)SEQ * DIM];
__device__ __half g_vth[(size_t)DIM * SEQ];                  // V^T fp16
__device__ __half g_ph[(size_t)SEQ * SEQ];                   // probs fp16

// ======================= helpers ===========================================
__device__ __forceinline__ uint32_t smem_u32(const void* p) {
    uint32_t a;
    asm("{ .reg .u64 t; cvta.to.shared.u64 t, %1; cvt.u32.u64 %0, t; }"
        : "=r"(a) : "l"(p));
    return a;
}
__device__ __forceinline__ void cpasync16(uint32_t dst, const void* src) {
    asm volatile("cp.async.cg.shared.global [%0], [%1], 16;"
                 :: "r"(dst), "l"(src));
}
#define CP_COMMIT() asm volatile("cp.async.commit_group;" ::: "memory")
#define CP_WAIT(n)  asm volatile("cp.async.wait_group %0;" :: "n"(n) : "memory")

#define LDSM4(r0, r1, r2, r3, addr)                                          \
    asm volatile("ldmatrix.sync.aligned.m8n8.x4.shared.b16 {%0,%1,%2,%3}, [%4];" \
                 : "=r"(r0), "=r"(r1), "=r"(r2), "=r"(r3) : "r"(addr))

#define MMAF16(c, a0, a1, a2, a3, b0, b1)                                    \
    asm volatile("mma.sync.aligned.m16n8k16.row.col.f32.f16.f16.f32 "        \
                 "{%0,%1,%2,%3}, {%4,%5,%6,%7}, {%8,%9}, {%0,%1,%2,%3};"     \
                 : "+f"((c)[0]), "+f"((c)[1]), "+f"((c)[2]), "+f"((c)[3])    \
                 : "r"(a0), "r"(a1), "r"(a2), "r"(a3), "r"(b0), "r"(b1))

__device__ __forceinline__ void split2h(float v, __half& h, __half& l) {
    h = __float2half_rn(v);
    l = __float2half_rn(v - __half2float(h));
}

// ======================= GEMM: C[M,N] = alpha*(A @ B^T) + bias =============
// A [M,K] fp16 (split A1+A2 when TERMS=3), B [N,K] fp16 (split B1+B2 when
// TERMS>=2), K-major. CTA tile 128x128, BK=32, 8 warps (2x4), warp tile
// 64x32. SW64-swizzled smem, 3-stage cp.async pipeline, 2 CTAs/SM.
// TERMS=3: A1B1+A1B2+A2B1.  TERMS=2: A1B1+A1B2.  TERMS=1: A1B1.
enum { EPI_F32 = 0, EPI_SPLIT = 1, EPI_SPLIT_T = 2, EPI_H_T = 3 };

struct GArgs {
    const __half* A1;
    const __half* A2;
    const __half* B1[3];
    const __half* B2[3];
    const float*  bias[3];
    float*        Cf;
    __half*       Ch[3];
    __half*       Cl[3];
    int           epi[3];
    int M, N, K, ldct;
    float alpha;
};

// swizzled byte offset inside an 8KB (128 rows x 64B) region
__device__ __forceinline__ uint32_t sw64(uint32_t r, uint32_t c16) {
    return r * 64 + (((c16 ^ ((r >> 1) & 3)) & 3) << 4);
}

template <int TERMS>
__global__ __launch_bounds__(256, 2)
void gemm_mma(const GArgs ga) {
    constexpr bool ASPL = (TERMS == 3);
    constexpr bool BSPL = (TERMS >= 2);
    constexpr uint32_t R_SZ = 8192;                 // one matrix region
    constexpr uint32_t OFF_A2 = R_SZ;               // (3-term only)
    constexpr uint32_t OFF_B1 = ASPL ? 2 * R_SZ : R_SZ;
    constexpr uint32_t OFF_B2 = OFF_B1 + R_SZ;      // (2/3-term only)
    constexpr uint32_t STG = OFF_B1 + (BSPL ? 2 : 1) * R_SZ; // 32K/24K/16K

    extern __shared__ char smem[];
    const uint32_t sb = smem_u32(smem);
    const int tid = threadIdx.x;
    const int lane = tid & 31;
    const int w = tid >> 5;
    const int wm = w >> 2;              // 0..1
    const int wn = w & 3;               // 0..3
    const int z = blockIdx.z;
    const int row0 = blockIdx.y * 128;
    const int col0 = blockIdx.x * 128;

    const __half* __restrict__ A1 = ga.A1;
    const __half* __restrict__ A2 = ga.A2;
    const __half* __restrict__ B1g = ga.B1[z];
    const __half* __restrict__ B2g = ga.B2[z];
    const int K = ga.K;

    float acc[4][4][4] = {};
    const int nk = K >> 5;

    auto load_stage = [&](int slot, int kt) {
        uint32_t s0 = sb + (uint32_t)slot * STG;
        int k0 = kt << 5;
#pragma unroll
        for (int p = 0; p < 2; p++) {
            int idx = tid + p * 256;
            uint32_t r = idx >> 2, c = idx & 3;
            uint32_t d = s0 + sw64(r, c);
            size_t gA = (size_t)(row0 + r) * K + k0 + c * 8;
            size_t gB = (size_t)(col0 + r) * K + k0 + c * 8;
            cpasync16(d, A1 + gA);
            if (ASPL) cpasync16(d + OFF_A2, A2 + gA);
            cpasync16(d + OFF_B1, B1g + gB);
            if (BSPL) cpasync16(d + OFF_B2, B2g + gB);
        }
    };

    // per-lane ldmatrix swizzled base offsets (bytes within region)
    const uint32_t r0a = (lane & 7) + ((lane >> 3) & 1) * 8 + wm * 64;
    const uint32_t swa = ((r0a >> 1) & 3) << 4;
    const uint32_t aoff = r0a * 64 + ((((lane >> 4) & 1) << 4) ^ swa);
    const uint32_t r0b = (lane & 7) + ((lane >> 4) & 1) * 8 + wn * 32;
    const uint32_t swb = ((r0b >> 1) & 3) << 4;
    const uint32_t boff = r0b * 64 + ((((lane >> 3) & 1) << 4) ^ swb);

    load_stage(0, 0);
    CP_COMMIT();
    load_stage(1, 1);
    CP_COMMIT();

    int slot = 0;
    for (int kt = 0; kt < nk; kt++) {
        CP_WAIT(1);
        __syncthreads();
        if (kt + 2 < nk) {
            int ns = slot + 2; if (ns >= 3) ns -= 3;
            load_stage(ns, kt + 2);
        }
        CP_COMMIT();

        const uint32_t s0 = sb + (uint32_t)slot * STG;
        const uint32_t aB = s0 + aoff;
        const uint32_t bB = s0 + OFF_B1 + boff;
#pragma unroll
        for (int ks = 0; ks < 2; ks++) {
            uint32_t a1[4][4], a2[4][4];
#pragma unroll
            for (int mi = 0; mi < 4; mi++) {
                uint32_t a = (aB + mi * 1024) ^ (ks << 5);
                LDSM4(a1[mi][0], a1[mi][1], a1[mi][2], a1[mi][3], a);
                if (ASPL) LDSM4(a2[mi][0], a2[mi][1], a2[mi][2], a2[mi][3],
                                a + OFF_A2);
            }
            uint32_t b1[4][2], b2[4][2];
#pragma unroll
            for (int j = 0; j < 2; j++) {
                uint32_t b = (bB + j * 1024) ^ (ks << 5);
                LDSM4(b1[2 * j][0], b1[2 * j][1], b1[2 * j + 1][0],
                      b1[2 * j + 1][1], b);
                if (BSPL)
                    LDSM4(b2[2 * j][0], b2[2 * j][1], b2[2 * j + 1][0],
                          b2[2 * j + 1][1], b + R_SZ);
            }
#pragma unroll
            for (int mi = 0; mi < 4; mi++)
#pragma unroll
                for (int ni = 0; ni < 4; ni++) {
                    MMAF16(acc[mi][ni], a1[mi][0], a1[mi][1], a1[mi][2], a1[mi][3],
                           b1[ni][0], b1[ni][1]);
                    if (BSPL)
                        MMAF16(acc[mi][ni], a1[mi][0], a1[mi][1], a1[mi][2], a1[mi][3],
                               b2[ni][0], b2[ni][1]);
                    if (ASPL)
                        MMAF16(acc[mi][ni], a2[mi][0], a2[mi][1], a2[mi][2], a2[mi][3],
                               b1[ni][0], b1[ni][1]);
                }
        }
        slot++; if (slot >= 3) slot = 0;
    }

    CP_WAIT(0);
    __syncthreads();

    const int tr = lane >> 2;          // 0..7
    const int tc = (lane & 3) * 2;     // 0,2,4,6
    const int epi = ga.epi[z];
    const float* bias = ga.bias[z];
    const float alpha = ga.alpha;

    if (epi == EPI_SPLIT_T || epi == EPI_H_T) {
        __half* __restrict__ Ch = ga.Ch[z];
        __half* __restrict__ Cl = ga.Cl[z];
        float* T = reinterpret_cast<float*>(smem);   // [128][133] = 68KB
#pragma unroll
        for (int mi = 0; mi < 4; mi++)
#pragma unroll
            for (int ni = 0; ni < 4; ni++) {
                int r = wm * 64 + mi * 16 + tr;
                int c = wn * 32 + ni * 8 + tc;
                T[r * 133 + c]           = acc[mi][ni][0];
                T[r * 133 + c + 1]       = acc[mi][ni][1];
                T[(r + 8) * 133 + c]     = acc[mi][ni][2];
                T[(r + 8) * 133 + c + 1] = acc[mi][ni][3];
            }
        __syncthreads();
        const int m = tid & 127;
        const int half = tid >> 7;
#pragma unroll 1
        for (int n = half; n < 128; n += 2) {
            float v = T[m * 133 + n] * alpha + bias[col0 + n];
            size_t o = (size_t)(col0 + n) * ga.ldct + row0 + m;
            if (epi == EPI_H_T) {
                Ch[o] = __float2half_rn(v);
            } else {
                __half h, l;
                split2h(v, h, l);
                Ch[o] = h;
                Cl[o] = l;
            }
        }
    } else if (epi == EPI_SPLIT) {
        __half* __restrict__ Ch = ga.Ch[z];
        __half* __restrict__ Cl = ga.Cl[z];
        const int N = ga.N;
#pragma unroll
        for (int mi = 0; mi < 4; mi++)
#pragma unroll
            for (int ni = 0; ni < 4; ni++) {
                int r = row0 + wm * 64 + mi * 16 + tr;
                int c = col0 + wn * 32 + ni * 8 + tc;
#pragma unroll
                for (int hh = 0; hh < 2; hh++) {
                    int rr = r + hh * 8;
                    float v0 = acc[mi][ni][2 * hh + 0] * alpha + bias[c];
                    float v1 = acc[mi][ni][2 * hh + 1] * alpha + bias[c + 1];
                    __half h0, l0, h1, l1;
                    split2h(v0, h0, l0);
                    split2h(v1, h1, l1);
                    *reinterpret_cast<__half2*>(&Ch[(size_t)rr * N + c]) =
                        __halves2half2(h0, h1);
                    *reinterpret_cast<__half2*>(&Cl[(size_t)rr * N + c]) =
                        __halves2half2(l0, l1);
                }
            }
    } else {  // EPI_F32
        float* __restrict__ Cf = ga.Cf;
        const int N = ga.N;
#pragma unroll
        for (int mi = 0; mi < 4; mi++)
#pragma unroll
            for (int ni = 0; ni < 4; ni++) {
                int r = row0 + wm * 64 + mi * 16 + tr;
                int c = col0 + wn * 32 + ni * 8 + tc;
#pragma unroll
                for (int hh = 0; hh < 2; hh++) {
                    int rr = r + hh * 8;
                    float2 f2 = make_float2(acc[mi][ni][2 * hh + 0] * alpha,
                                            acc[mi][ni][2 * hh + 1] * alpha);
                    *reinterpret_cast<float2*>(&Cf[(size_t)rr * N + c]) = f2;
                }
            }
    }
}

// ======================= elementwise split (x) =============================
__global__ __launch_bounds__(256)
void split_kernel(const float* __restrict__ in, __half* __restrict__ hi,
                  __half* __restrict__ lo, int n4) {
    int i = blockIdx.x * 256 + threadIdx.x;
    if (i >= n4) return;
    float4 v = reinterpret_cast<const float4*>(in)[i];
    __half h[4], l[4];
    split2h(v.x, h[0], l[0]);
    split2h(v.y, h[1], l[1]);
    split2h(v.z, h[2], l[2]);
    split2h(v.w, h[3], l[3]);
    reinterpret_cast<uint2*>(hi)[i] = *reinterpret_cast<uint2*>(h);
    reinterpret_cast<uint2*>(lo)[i] = *reinterpret_cast<uint2*>(l);
}

// ======================= split + transpose (3 W's, fused) ==================
struct TArgs {
    const float* in[3];
    __half* hiT[3];
    __half* loT[3];
};
__global__ __launch_bounds__(256)
void splitT3_kernel(const TArgs ta, int R, int C) {
    __shared__ float t[32][33];
    const int z = blockIdx.z;
    const float* __restrict__ in = ta.in[z];
    __half* __restrict__ hiT = ta.hiT[z];
    __half* __restrict__ loT = ta.loT[z];
    const int tx = threadIdx.x & 31, ty = threadIdx.x >> 5;
    const int bc = blockIdx.x * 32, br = blockIdx.y * 32;
#pragma unroll
    for (int j = 0; j < 4; j++)
        t[ty + 8 * j][tx] = in[(size_t)(br + ty + 8 * j) * C + bc + tx];
    __syncthreads();
#pragma unroll
    for (int j = 0; j < 4; j++) {
        int cc = ty + 8 * j;
        __half h, l;
        split2h(t[tx][cc], h, l);
        hiT[(size_t)(bc + cc) * R + br + tx] = h;
        loT[(size_t)(bc + cc) * R + br + tx] = l;
    }
}

// ======================= softmax rows -> fp16 probs ========================
__global__ __launch_bounds__(256)
void softmax_h(const float* __restrict__ S, __half* __restrict__ ph, int n) {
    const int row = blockIdx.x;
    const float4* p = reinterpret_cast<const float4*>(S + (size_t)row * n);
    const int nv = n / 4;
    const int tid = threadIdx.x;
    __shared__ float red[256];

    float m = -INFINITY;
    for (int i = tid; i < nv; i += 256) {
        float4 v = p[i];
        m = fmaxf(m, fmaxf(fmaxf(v.x, v.y), fmaxf(v.z, v.w)));
    }
    red[tid] = m;
    __syncthreads();
    for (int s = 128; s > 0; s >>= 1) {
        if (tid < s) red[tid] = fmaxf(red[tid], red[tid + s]);
        __syncthreads();
    }
    m = red[0];
    __syncthreads();

    float sum = 0.0f;
    for (int i = tid; i < nv; i += 256) {
        float4 v = p[i];
        sum += (expf(v.x - m) + expf(v.y - m)) + (expf(v.z - m) + expf(v.w - m));
    }
    red[tid] = sum;
    __syncthreads();
    for (int s = 128; s > 0; s >>= 1) {
        if (tid < s) red[tid] += red[tid + s];
        __syncthreads();
    }
    const float inv = 1.0f / red[0];
    __syncthreads();

    for (int i = tid; i < nv; i += 256) {
        float4 v = p[i];
        __half h[4];
        h[0] = __float2half_rn(expf(v.x - m) * inv);
        h[1] = __float2half_rn(expf(v.y - m) * inv);
        h[2] = __float2half_rn(expf(v.z - m) * inv);
        h[3] = __float2half_rn(expf(v.w - m) * inv);
        reinterpret_cast<uint2*>(ph + (size_t)row * n)[i] =
            *reinterpret_cast<uint2*>(h);
    }
}

// ======================= launch ============================================
extern "C" void kernel_launch(void* const* d_in, const int* in_sizes, int n_in,
                              void* d_out, int out_size) {
    const float* x  = (const float*)d_in[0];
    const float* WQ = (const float*)d_in[1];
    const float* WK = (const float*)d_in[2];
    const float* WV = (const float*)d_in[3];
    const float* bQ = (const float*)d_in[4];
    const float* bK = (const float*)d_in[5];
    const float* bV = (const float*)d_in[6];
    float* out = (float*)d_out;

    float* S;
    __half *xh, *xl, *wqh, *wql, *wkh, *wkl, *wvh, *wvl;
    __half *qh, *ql, *kh, *kl, *vth, *ph;
    cudaGetSymbolAddress((void**)&S, g_S);
    cudaGetSymbolAddress((void**)&xh, g_xh);   cudaGetSymbolAddress((void**)&xl, g_xl);
    cudaGetSymbolAddress((void**)&wqh, g_wqh); cudaGetSymbolAddress((void**)&wql, g_wql);
    cudaGetSymbolAddress((void**)&wkh, g_wkh); cudaGetSymbolAddress((void**)&wkl, g_wkl);
    cudaGetSymbolAddress((void**)&wvh, g_wvh); cudaGetSymbolAddress((void**)&wvl, g_wvl);
    cudaGetSymbolAddress((void**)&qh, g_qh);   cudaGetSymbolAddress((void**)&ql, g_ql);
    cudaGetSymbolAddress((void**)&kh, g_kh);   cudaGetSymbolAddress((void**)&kl, g_kl);
    cudaGetSymbolAddress((void**)&vth, g_vth);
    cudaGetSymbolAddress((void**)&ph, g_ph);

    constexpr int SM_3T = 3 * 32768;   // 98304 per CTA -> 2 CTAs/SM
    constexpr int SM_1T = 3 * 16384;   // 49152 per CTA -> 2 CTAs/SM

    cudaFuncSetAttribute((const void*)gemm_mma<3>,
                         cudaFuncAttributeMaxDynamicSharedMemorySize, SM_3T);
    cudaFuncSetAttribute((const void*)gemm_mma<1>,
                         cudaFuncAttributeMaxDynamicSharedMemorySize, SM_1T);

    // split inputs
    split_kernel<<<(SEQ * DIM / 4 + 255) / 256, 256>>>(x, xh, xl, SEQ * DIM / 4);
    {
        TArgs ta = {};
        ta.in[0] = WQ;  ta.in[1] = WK;  ta.in[2] = WV;
        ta.hiT[0] = wqh; ta.hiT[1] = wkh; ta.hiT[2] = wvh;
        ta.loT[0] = wql; ta.loT[1] = wkl; ta.loT[2] = wvl;
        dim3 gT(DIM / 32, DIM / 32, 3);
        splitT3_kernel<<<gT, 256>>>(ta, DIM, DIM);
    }

    // fused QKV projections: z=0 -> Q (split), z=1 -> K (split), z=2 -> V^T (fp16)
    {
        GArgs ga = {};
        ga.A1 = xh; ga.A2 = xl;
        ga.B1[0] = wqh; ga.B1[1] = wkh; ga.B1[2] = wvh;
        ga.B2[0] = wql; ga.B2[1] = wkl; ga.B2[2] = wvl;
        ga.bias[0] = bQ; ga.bias[1] = bK; ga.bias[2] = bV;
        ga.Ch[0] = qh; ga.Ch[1] = kh; ga.Ch[2] = vth;
        ga.Cl[0] = ql; ga.Cl[1] = kl; ga.Cl[2] = nullptr;
        ga.epi[0] = EPI_SPLIT; ga.epi[1] = EPI_SPLIT; ga.epi[2] = EPI_H_T;
        ga.M = SEQ; ga.N = DIM; ga.K = DIM; ga.ldct = SEQ; ga.alpha = 1.0f;
        dim3 g(DIM / 128, SEQ / 128, 3);
        gemm_mma<3><<<g, 256, SM_3T>>>(ga);
    }

    // scores: S = (Q @ K^T) / 32
    {
        GArgs ga = {};
        ga.A1 = qh; ga.A2 = ql;
        ga.B1[0] = kh; ga.B2[0] = kl;
        ga.Cf = S;
        ga.epi[0] = EPI_F32;
        ga.M = SEQ; ga.N = SEQ; ga.K = DIM; ga.ldct = 0; ga.alpha = 0.03125f;
        dim3 g(SEQ / 128, SEQ / 128, 1);
        gemm_mma<3><<<g, 256, SM_3T>>>(ga);
    }

    // softmax rows -> single fp16 probs
    softmax_h<<<SEQ, 256>>>(S, ph, SEQ);

    // out = P @ V  (A = P fp16, B = V^T fp16; TERMS=1)
    {
        GArgs ga = {};
        ga.A1 = ph; ga.A2 = nullptr;
        ga.B1[0] = vth; ga.B2[0] = nullptr;
        ga.Cf = out;
        ga.epi[0] = EPI_F32;
        ga.M = SEQ; ga.N = DIM; ga.K = SEQ; ga.ldct = 0; ga.alpha = 1.0f;
        dim3 g(DIM / 128, SEQ / 128, 1);
        gemm_mma<1><<<g, 256, SM_1T>>>(ga);
    }
}

// round 7
// speedup vs baseline: 3.7659x; 1.0110x over previous
#include <cuda_runtime.h>
#include <cuda_fp16.h>
#include <math.h>
#include <stdint.h>

#define SEQ 4096
#define DIM 1024

// ======================= device scratch (no cudaMalloc) ====================
__device__ float  g_S[(size_t)SEQ * SEQ];                    // scores fp32
__device__ __half g_xh[(size_t)SEQ * DIM],  g_xl[(size_t)SEQ * DIM];
__device__ __half g_wqh[(size_t)DIM * DIM], g_wql[(size_t)DIM * DIM];
__device__ __half g_wkh[(size_t)DIM * DIM], g_wkl[(size_t)DIM * DIM];
__device__ __half g_wvh[(size_t)DIM * DIM], g_wvl[(size_t)DIM * DIM];
__device__ __half g_qh[(size_t)SEQ * DIM],  g_ql[(size_t)SEQ * DIM];
__device__ __half g_kh[(size_t)SEQ * DIM],  g_kl[(size_t)SEQ * DIM];
__device__ __half g_vth[(size_t)DIM * SEQ];                  // V^T fp16
__device__ __half g_ph[(size_t)SEQ * SEQ];                   // probs fp16

// ======================= helpers ===========================================
__device__ __forceinline__ uint32_t smem_u32(const void* p) {
    uint32_t a;
    asm("{ .reg .u64 t; cvta.to.shared.u64 t, %1; cvt.u32.u64 %0, t; }"
        : "=r"(a) : "l"(p));
    return a;
}
__device__ __forceinline__ void cpasync16(uint32_t dst, const void* src) {
    asm volatile("cp.async.cg.shared.global [%0], [%1], 16;"
                 :: "r"(dst), "l"(src));
}
#define CP_COMMIT() asm volatile("cp.async.commit_group;" ::: "memory")
#define CP_WAIT(n)  asm volatile("cp.async.wait_group %0;" :: "n"(n) : "memory")

#define LDSM4(r0, r1, r2, r3, addr)                                          \
    asm volatile("ldmatrix.sync.aligned.m8n8.x4.shared.b16 {%0,%1,%2,%3}, [%4];" \
                 : "=r"(r0), "=r"(r1), "=r"(r2), "=r"(r3) : "r"(addr))

#define MMAF16(c, a0, a1, a2, a3, b0, b1)                                    \
    asm volatile("mma.sync.aligned.m16n8k16.row.col.f32.f16.f16.f32 "        \
                 "{%0,%1,%2,%3}, {%4,%5,%6,%7}, {%8,%9}, {%0,%1,%2,%3};"     \
                 : "+f"((c)[0]), "+f"((c)[1]), "+f"((c)[2]), "+f"((c)[3])    \
                 : "r"(a0), "r"(a1), "r"(a2), "r"(a3), "r"(b0), "r"(b1))

__device__ __forceinline__ void split2h(float v, __half& h, __half& l) {
    h = __float2half_rn(v);
    l = __float2half_rn(v - __half2float(h));
}

// ======================= GEMM: C[M,N] = alpha*(A @ B^T) + bias =============
// A [M,K] fp16 (split A1+A2 when TERMS=3), B [N,K] fp16 (split B1+B2 when
// TERMS>=2), K-major. CTA tile 128x128, BK=32 per chunk, CPS chunks per
// pipeline stage. 8 warps (2x4), warp tile 64x32. SW64-swizzled smem,
// 3-stage cp.async pipeline, 2 CTAs/SM.
enum { EPI_F32 = 0, EPI_SPLIT = 1, EPI_SPLIT_T = 2, EPI_H_T = 3 };

struct GArgs {
    const __half* A1;
    const __half* A2;
    const __half* B1[3];
    const __half* B2[3];
    const float*  bias[3];
    float*        Cf;
    __half*       Ch[3];
    __half*       Cl[3];
    int           epi[3];
    int M, N, K, ldct;
    float alpha;
};

// swizzled byte offset inside an 8KB (128 rows x 64B) region
__device__ __forceinline__ uint32_t sw64(uint32_t r, uint32_t c16) {
    return r * 64 + (((c16 ^ ((r >> 1) & 3)) & 3) << 4);
}

template <int TERMS, int CPS>
__global__ __launch_bounds__(256, 2)
void gemm_mma(const GArgs ga) {
    constexpr bool ASPL = (TERMS == 3);
    constexpr bool BSPL = (TERMS >= 2);
    constexpr uint32_t R_SZ = 8192;                 // one matrix region
    constexpr uint32_t OFF_A2 = R_SZ;               // (3-term only)
    constexpr uint32_t OFF_B1 = ASPL ? 2 * R_SZ : R_SZ;
    constexpr uint32_t OFF_B2 = OFF_B1 + R_SZ;      // (2/3-term only)
    constexpr uint32_t CHUNK = OFF_B1 + (BSPL ? 2 : 1) * R_SZ; // bytes/chunk
    constexpr uint32_t STG = CPS * CHUNK;           // bytes per stage

    extern __shared__ char smem[];
    const uint32_t sb = smem_u32(smem);
    const int tid = threadIdx.x;
    const int lane = tid & 31;
    const int w = tid >> 5;
    const int wm = w >> 2;              // 0..1
    const int wn = w & 3;               // 0..3
    const int z = blockIdx.z;
    const int row0 = blockIdx.y * 128;
    const int col0 = blockIdx.x * 128;

    const __half* __restrict__ A1 = ga.A1;
    const __half* __restrict__ A2 = ga.A2;
    const __half* __restrict__ B1g = ga.B1[z];
    const __half* __restrict__ B2g = ga.B2[z];
    const int K = ga.K;

    float acc[4][4][4] = {};
    const int nst = (K >> 5) / CPS;     // pipeline stages count

    auto load_stage = [&](int slot, int st) {
        uint32_t s0 = sb + (uint32_t)slot * STG;
#pragma unroll
        for (int h = 0; h < CPS; h++) {
            int k0 = (st * CPS + h) << 5;
            uint32_t c0 = s0 + h * CHUNK;
#pragma unroll
            for (int p = 0; p < 2; p++) {
                int idx = tid + p * 256;
                uint32_t r = idx >> 2, c = idx & 3;
                uint32_t d = c0 + sw64(r, c);
                size_t gA = (size_t)(row0 + r) * K + k0 + c * 8;
                size_t gB = (size_t)(col0 + r) * K + k0 + c * 8;
                cpasync16(d, A1 + gA);
                if (ASPL) cpasync16(d + OFF_A2, A2 + gA);
                cpasync16(d + OFF_B1, B1g + gB);
                if (BSPL) cpasync16(d + OFF_B2, B2g + gB);
            }
        }
    };

    // per-lane ldmatrix swizzled base offsets (bytes within region)
    const uint32_t r0a = (lane & 7) + ((lane >> 3) & 1) * 8 + wm * 64;
    const uint32_t swa = ((r0a >> 1) & 3) << 4;
    const uint32_t aoff = r0a * 64 + ((((lane >> 4) & 1) << 4) ^ swa);
    const uint32_t r0b = (lane & 7) + ((lane >> 4) & 1) * 8 + wn * 32;
    const uint32_t swb = ((r0b >> 1) & 3) << 4;
    const uint32_t boff = r0b * 64 + ((((lane >> 3) & 1) << 4) ^ swb);

    load_stage(0, 0);
    CP_COMMIT();
    load_stage(1, 1);
    CP_COMMIT();

    int slot = 0;
    for (int st = 0; st < nst; st++) {
        CP_WAIT(1);
        __syncthreads();
        if (st + 2 < nst) {
            int ns = slot + 2; if (ns >= 3) ns -= 3;
            load_stage(ns, st + 2);
        }
        CP_COMMIT();

#pragma unroll
        for (int h = 0; h < CPS; h++) {
            const uint32_t s0 = sb + (uint32_t)slot * STG + h * CHUNK;
            const uint32_t aB = s0 + aoff;
            const uint32_t bB = s0 + OFF_B1 + boff;
#pragma unroll
            for (int ks = 0; ks < 2; ks++) {
                uint32_t a1[4][4], a2[4][4];
#pragma unroll
                for (int mi = 0; mi < 4; mi++) {
                    uint32_t a = (aB + mi * 1024) ^ (ks << 5);
                    LDSM4(a1[mi][0], a1[mi][1], a1[mi][2], a1[mi][3], a);
                    if (ASPL) LDSM4(a2[mi][0], a2[mi][1], a2[mi][2], a2[mi][3],
                                    a + OFF_A2);
                }
                uint32_t b1[4][2], b2[4][2];
#pragma unroll
                for (int j = 0; j < 2; j++) {
                    uint32_t b = (bB + j * 1024) ^ (ks << 5);
                    LDSM4(b1[2 * j][0], b1[2 * j][1], b1[2 * j + 1][0],
                          b1[2 * j + 1][1], b);
                    if (BSPL)
                        LDSM4(b2[2 * j][0], b2[2 * j][1], b2[2 * j + 1][0],
                              b2[2 * j + 1][1], b + R_SZ);
                }
#pragma unroll
                for (int mi = 0; mi < 4; mi++)
#pragma unroll
                    for (int ni = 0; ni < 4; ni++) {
                        MMAF16(acc[mi][ni], a1[mi][0], a1[mi][1], a1[mi][2],
                               a1[mi][3], b1[ni][0], b1[ni][1]);
                        if (BSPL)
                            MMAF16(acc[mi][ni], a1[mi][0], a1[mi][1], a1[mi][2],
                                   a1[mi][3], b2[ni][0], b2[ni][1]);
                        if (ASPL)
                            MMAF16(acc[mi][ni], a2[mi][0], a2[mi][1], a2[mi][2],
                                   a2[mi][3], b1[ni][0], b1[ni][1]);
                    }
            }
        }
        slot++; if (slot >= 3) slot = 0;
    }

    CP_WAIT(0);
    __syncthreads();

    const int tr = lane >> 2;          // 0..7
    const int tc = (lane & 3) * 2;     // 0,2,4,6
    const int epi = ga.epi[z];
    const float* bias = ga.bias[z];
    const float alpha = ga.alpha;

    if (epi == EPI_SPLIT_T || epi == EPI_H_T) {
        __half* __restrict__ Ch = ga.Ch[z];
        __half* __restrict__ Cl = ga.Cl[z];
        float* T = reinterpret_cast<float*>(smem);   // [128][133] = 68KB
#pragma unroll
        for (int mi = 0; mi < 4; mi++)
#pragma unroll
            for (int ni = 0; ni < 4; ni++) {
                int r = wm * 64 + mi * 16 + tr;
                int c = wn * 32 + ni * 8 + tc;
                T[r * 133 + c]           = acc[mi][ni][0];
                T[r * 133 + c + 1]       = acc[mi][ni][1];
                T[(r + 8) * 133 + c]     = acc[mi][ni][2];
                T[(r + 8) * 133 + c + 1] = acc[mi][ni][3];
            }
        __syncthreads();
        const int m = tid & 127;
        const int half = tid >> 7;
#pragma unroll 1
        for (int n = half; n < 128; n += 2) {
            float v = T[m * 133 + n] * alpha + bias[col0 + n];
            size_t o = (size_t)(col0 + n) * ga.ldct + row0 + m;
            if (epi == EPI_H_T) {
                Ch[o] = __float2half_rn(v);
            } else {
                __half h, l;
                split2h(v, h, l);
                Ch[o] = h;
                Cl[o] = l;
            }
        }
    } else if (epi == EPI_SPLIT) {
        __half* __restrict__ Ch = ga.Ch[z];
        __half* __restrict__ Cl = ga.Cl[z];
        const int N = ga.N;
#pragma unroll
        for (int mi = 0; mi < 4; mi++)
#pragma unroll
            for (int ni = 0; ni < 4; ni++) {
                int r = row0 + wm * 64 + mi * 16 + tr;
                int c = col0 + wn * 32 + ni * 8 + tc;
#pragma unroll
                for (int hh = 0; hh < 2; hh++) {
                    int rr = r + hh * 8;
                    float v0 = acc[mi][ni][2 * hh + 0] * alpha + bias[c];
                    float v1 = acc[mi][ni][2 * hh + 1] * alpha + bias[c + 1];
                    __half h0, l0, h1, l1;
                    split2h(v0, h0, l0);
                    split2h(v1, h1, l1);
                    *reinterpret_cast<__half2*>(&Ch[(size_t)rr * N + c]) =
                        __halves2half2(h0, h1);
                    *reinterpret_cast<__half2*>(&Cl[(size_t)rr * N + c]) =
                        __halves2half2(l0, l1);
                }
            }
    } else {  // EPI_F32
        float* __restrict__ Cf = ga.Cf;
        const int N = ga.N;
#pragma unroll
        for (int mi = 0; mi < 4; mi++)
#pragma unroll
            for (int ni = 0; ni < 4; ni++) {
                int r = row0 + wm * 64 + mi * 16 + tr;
                int c = col0 + wn * 32 + ni * 8 + tc;
#pragma unroll
                for (int hh = 0; hh < 2; hh++) {
                    int rr = r + hh * 8;
                    float2 f2 = make_float2(acc[mi][ni][2 * hh + 0] * alpha,
                                            acc[mi][ni][2 * hh + 1] * alpha);
                    *reinterpret_cast<float2*>(&Cf[(size_t)rr * N + c]) = f2;
                }
            }
    }
}

// ======================= elementwise split (x) =============================
__global__ __launch_bounds__(256)
void split_kernel(const float* __restrict__ in, __half* __restrict__ hi,
                  __half* __restrict__ lo, int n4) {
    int i = blockIdx.x * 256 + threadIdx.x;
    if (i >= n4) return;
    float4 v = reinterpret_cast<const float4*>(in)[i];
    __half h[4], l[4];
    split2h(v.x, h[0], l[0]);
    split2h(v.y, h[1], l[1]);
    split2h(v.z, h[2], l[2]);
    split2h(v.w, h[3], l[3]);
    reinterpret_cast<uint2*>(hi)[i] = *reinterpret_cast<uint2*>(h);
    reinterpret_cast<uint2*>(lo)[i] = *reinterpret_cast<uint2*>(l);
}

// ======================= split + transpose (3 W's, fused) ==================
struct TArgs {
    const float* in[3];
    __half* hiT[3];
    __half* loT[3];
};
__global__ __launch_bounds__(256)
void splitT3_kernel(const TArgs ta, int R, int C) {
    __shared__ float t[32][33];
    const int z = blockIdx.z;
    const float* __restrict__ in = ta.in[z];
    __half* __restrict__ hiT = ta.hiT[z];
    __half* __restrict__ loT = ta.loT[z];
    const int tx = threadIdx.x & 31, ty = threadIdx.x >> 5;
    const int bc = blockIdx.x * 32, br = blockIdx.y * 32;
#pragma unroll
    for (int j = 0; j < 4; j++)
        t[ty + 8 * j][tx] = in[(size_t)(br + ty + 8 * j) * C + bc + tx];
    __syncthreads();
#pragma unroll
    for (int j = 0; j < 4; j++) {
        int cc = ty + 8 * j;
        __half h, l;
        split2h(t[tx][cc], h, l);
        hiT[(size_t)(bc + cc) * R + br + tx] = h;
        loT[(size_t)(bc + cc) * R + br + tx] = l;
    }
}

// ======================= softmax: register-resident, 1 read, 1 exp =========
// One block per row (n = 4096, 256 threads, 16 floats/thread in registers).
__global__ __launch_bounds__(256)
void softmax_reg(const float* __restrict__ S, __half* __restrict__ ph, int n) {
    const int row = blockIdx.x;
    const int tid = threadIdx.x;
    const float4* p = reinterpret_cast<const float4*>(S + (size_t)row * n);
    __shared__ float red[256];

    float v[16];
    float m = -INFINITY;
#pragma unroll
    for (int j = 0; j < 4; j++) {
        float4 q = p[tid + 256 * j];
        v[4 * j + 0] = q.x; v[4 * j + 1] = q.y;
        v[4 * j + 2] = q.z; v[4 * j + 3] = q.w;
        m = fmaxf(m, fmaxf(fmaxf(q.x, q.y), fmaxf(q.z, q.w)));
    }
    red[tid] = m;
    __syncthreads();
    for (int s = 128; s > 0; s >>= 1) {
        if (tid < s) red[tid] = fmaxf(red[tid], red[tid + s]);
        __syncthreads();
    }
    m = red[0];
    __syncthreads();

    float sum = 0.0f;
#pragma unroll
    for (int j = 0; j < 16; j++) {
        v[j] = expf(v[j] - m);
        sum += v[j];
    }
    red[tid] = sum;
    __syncthreads();
    for (int s = 128; s > 0; s >>= 1) {
        if (tid < s) red[tid] += red[tid + s];
        __syncthreads();
    }
    const float inv = 1.0f / red[0];

    uint2* outp = reinterpret_cast<uint2*>(ph + (size_t)row * n);
#pragma unroll
    for (int j = 0; j < 4; j++) {
        __half h[4];
        h[0] = __float2half_rn(v[4 * j + 0] * inv);
        h[1] = __float2half_rn(v[4 * j + 1] * inv);
        h[2] = __float2half_rn(v[4 * j + 2] * inv);
        h[3] = __float2half_rn(v[4 * j + 3] * inv);
        outp[tid + 256 * j] = *reinterpret_cast<uint2*>(h);
    }
}

// ======================= launch ============================================
extern "C" void kernel_launch(void* const* d_in, const int* in_sizes, int n_in,
                              void* d_out, int out_size) {
    const float* x  = (const float*)d_in[0];
    const float* WQ = (const float*)d_in[1];
    const float* WK = (const float*)d_in[2];
    const float* WV = (const float*)d_in[3];
    const float* bQ = (const float*)d_in[4];
    const float* bK = (const float*)d_in[5];
    const float* bV = (const float*)d_in[6];
    float* out = (float*)d_out;

    float* S;
    __half *xh, *xl, *wqh, *wql, *wkh, *wkl, *wvh, *wvl;
    __half *qh, *ql, *kh, *kl, *vth, *ph;
    cudaGetSymbolAddress((void**)&S, g_S);
    cudaGetSymbolAddress((void**)&xh, g_xh);   cudaGetSymbolAddress((void**)&xl, g_xl);
    cudaGetSymbolAddress((void**)&wqh, g_wqh); cudaGetSymbolAddress((void**)&wql, g_wql);
    cudaGetSymbolAddress((void**)&wkh, g_wkh); cudaGetSymbolAddress((void**)&wkl, g_wkl);
    cudaGetSymbolAddress((void**)&wvh, g_wvh); cudaGetSymbolAddress((void**)&wvl, g_wvl);
    cudaGetSymbolAddress((void**)&qh, g_qh);   cudaGetSymbolAddress((void**)&ql, g_ql);
    cudaGetSymbolAddress((void**)&kh, g_kh);   cudaGetSymbolAddress((void**)&kl, g_kl);
    cudaGetSymbolAddress((void**)&vth, g_vth);
    cudaGetSymbolAddress((void**)&ph, g_ph);

    constexpr int SM_3T = 3 * 32768;   // 98304/CTA -> 2 CTAs/SM (TERMS=3,CPS=1)
    constexpr int SM_1T = 3 * 32768;   // 98304/CTA -> 2 CTAs/SM (TERMS=1,CPS=2)

    cudaFuncSetAttribute((const void*)gemm_mma<3, 1>,
                         cudaFuncAttributeMaxDynamicSharedMemorySize, SM_3T);
    cudaFuncSetAttribute((const void*)gemm_mma<1, 2>,
                         cudaFuncAttributeMaxDynamicSharedMemorySize, SM_1T);

    // second stream for overlapping the V projection with the scores GEMM
    cudaStream_t s2;
    cudaStreamCreateWithFlags(&s2, cudaStreamNonBlocking);
    cudaEvent_t e1, e2;
    cudaEventCreateWithFlags(&e1, cudaEventDisableTiming);
    cudaEventCreateWithFlags(&e2, cudaEventDisableTiming);

    // ---- prologue splits (stream 0) ----
    split_kernel<<<(SEQ * DIM / 4 + 255) / 256, 256>>>(x, xh, xl, SEQ * DIM / 4);
    {
        TArgs ta = {};
        ta.in[0] = WQ;  ta.in[1] = WK;  ta.in[2] = WV;
        ta.hiT[0] = wqh; ta.hiT[1] = wkh; ta.hiT[2] = wvh;
        ta.loT[0] = wql; ta.loT[1] = wkl; ta.loT[2] = wvl;
        dim3 gT(DIM / 32, DIM / 32, 3);
        splitT3_kernel<<<gT, 256>>>(ta, DIM, DIM);
    }
    cudaEventRecord(e1, 0);
    cudaStreamWaitEvent(s2, e1, 0);

    // ---- V projection on s2 (overlaps QK proj + scores on stream 0) ----
    {
        GArgs ga = {};
        ga.A1 = xh; ga.A2 = xl;
        ga.B1[0] = wvh; ga.B2[0] = wvl;
        ga.bias[0] = bV;
        ga.Ch[0] = vth; ga.Cl[0] = nullptr;
        ga.epi[0] = EPI_H_T;
        ga.M = SEQ; ga.N = DIM; ga.K = DIM; ga.ldct = SEQ; ga.alpha = 1.0f;
        dim3 g(DIM / 128, SEQ / 128, 1);
        gemm_mma<3, 1><<<g, 256, SM_3T, s2>>>(ga);
    }
    cudaEventRecord(e2, s2);

    // ---- Q,K projections (stream 0, z-fused) ----
    {
        GArgs ga = {};
        ga.A1 = xh; ga.A2 = xl;
        ga.B1[0] = wqh; ga.B1[1] = wkh;
        ga.B2[0] = wql; ga.B2[1] = wkl;
        ga.bias[0] = bQ; ga.bias[1] = bK;
        ga.Ch[0] = qh; ga.Ch[1] = kh;
        ga.Cl[0] = ql; ga.Cl[1] = kl;
        ga.epi[0] = EPI_SPLIT; ga.epi[1] = EPI_SPLIT;
        ga.M = SEQ; ga.N = DIM; ga.K = DIM; ga.ldct = 0; ga.alpha = 1.0f;
        dim3 g(DIM / 128, SEQ / 128, 2);
        gemm_mma<3, 1><<<g, 256, SM_3T>>>(ga);
    }

    // ---- scores: S = (Q @ K^T) / 32 (stream 0) ----
    {
        GArgs ga = {};
        ga.A1 = qh; ga.A2 = ql;
        ga.B1[0] = kh; ga.B2[0] = kl;
        ga.Cf = S;
        ga.epi[0] = EPI_F32;
        ga.M = SEQ; ga.N = SEQ; ga.K = DIM; ga.ldct = 0; ga.alpha = 0.03125f;
        dim3 g(SEQ / 128, SEQ / 128, 1);
        gemm_mma<3, 1><<<g, 256, SM_3T>>>(ga);
    }

    // ---- softmax (stream 0) ----
    softmax_reg<<<SEQ, 256>>>(S, ph, SEQ);

    // ---- join V-proj, then PV (stream 0) ----
    cudaStreamWaitEvent(0, e2, 0);
    {
        GArgs ga = {};
        ga.A1 = ph; ga.A2 = nullptr;
        ga.B1[0] = vth; ga.B2[0] = nullptr;
        ga.Cf = out;
        ga.epi[0] = EPI_F32;
        ga.M = SEQ; ga.N = DIM; ga.K = SEQ; ga.ldct = 0; ga.alpha = 1.0f;
        dim3 g(DIM / 128, SEQ / 128, 1);
        gemm_mma<1, 2><<<g, 256, SM_1T>>>(ga);
    }

    cudaEventDestroy(e1);
    cudaEventDestroy(e2);
    cudaStreamDestroy(s2);
}